// round 5
// baseline (speedup 1.0000x reference)
#include <cuda_runtime.h>
#include <cuda_bf16.h>
#include <cstdint>

#define B_  8
#define C_  64
#define H_  128
#define W_  128
#define O_  64
#define HW_ (H_*W_)
#define K2_ 9

// Scratch (device globals; no allocation allowed)
__device__ float g_xt[B_*HW_*C_];              // x transposed to [b][h][w][c]
__device__ float g_off[B_*2*K2_*HW_];          // offsets planar [b][j][h][w]
__device__ __nv_bfloat16 g_wbh[K2_*4096];      // weight hi, swizzled [k][o(64) x c(64)]
__device__ __nv_bfloat16 g_wbl[K2_*4096];      // weight lo

// ---------------------------------------------------------------------------
__device__ __forceinline__ uint32_t smem_u32(const void* p) {
    uint32_t a;
    asm("{ .reg .u64 t; cvta.to.shared.u64 t, %1; cvt.u32.u64 %0, t; }"
        : "=r"(a) : "l"(p));
    return a;
}
__device__ __forceinline__ uint32_t cvt2bf(float hi, float lo) {
    uint32_t r;
    asm("cvt.rn.bf16x2.f32 %0, %1, %2;" : "=r"(r) : "f"(hi), "f"(lo));
    return r;
}
#define LDMX4(r, addr)                                                       \
    asm volatile("ldmatrix.sync.aligned.m8n8.x4.shared.b16 {%0,%1,%2,%3}, [%4];" \
        : "=r"((r)[0]), "=r"((r)[1]), "=r"((r)[2]), "=r"((r)[3]) : "r"(addr))
#define MMA16816(d, a, b0, b1)                                               \
    asm volatile("mma.sync.aligned.m16n8k16.row.col.f32.bf16.bf16.f32 "      \
        "{%0,%1,%2,%3}, {%4,%5,%6,%7}, {%8,%9}, {%0,%1,%2,%3};"              \
        : "+f"((d)[0]), "+f"((d)[1]), "+f"((d)[2]), "+f"((d)[3])             \
        : "r"((a)[0]), "r"((a)[1]), "r"((a)[2]), "r"((a)[3]),                \
          "r"(b0), "r"(b1))
#define BAR_ARRIVE(id) \
    asm volatile("bar.arrive %0, %1;" :: "r"(id), "r"(512) : "memory")
#define BAR_SYNC(id) \
    asm volatile("bar.sync %0, %1;" :: "r"(id), "r"(512) : "memory")

// ---------------------------------------------------------------------------
// Kernel 1: NCHW -> NHWC transpose of x
// ---------------------------------------------------------------------------
__global__ void k_transpose(const float* __restrict__ x) {
    __shared__ float tile[32][33];
    int b  = blockIdx.z;
    int c0 = blockIdx.y * 32;
    int p0 = blockIdx.x * 32;
    int tx = threadIdx.x, ty = threadIdx.y;
    const float* xb = x + (size_t)b * C_ * HW_;
#pragma unroll
    for (int i = 0; i < 32; i += 8)
        tile[ty + i][tx] = xb[(size_t)(c0 + ty + i) * HW_ + p0 + tx];
    __syncthreads();
    float* xtb = g_xt + (size_t)b * HW_ * C_;
#pragma unroll
    for (int i = 0; i < 32; i += 8)
        xtb[(size_t)(p0 + ty + i) * C_ + c0 + tx] = tile[tx][ty + i];
}

// ---------------------------------------------------------------------------
// Kernel 2: offsets  off[b,j,h,w] = sum_c x[b,c,h,w] * w_off[j,c] + b_off[j]
// ---------------------------------------------------------------------------
__global__ void k_offsets(const float* __restrict__ x,
                          const float* __restrict__ w_off,
                          const float* __restrict__ b_off) {
    __shared__ float sw[18 * 64];
    __shared__ float sb[18];
    int t = threadIdx.x;
    for (int i = t; i < 18 * 64; i += 256) sw[i] = w_off[i];
    if (t < 18) sb[t] = b_off[t];
    __syncthreads();

    int idx = blockIdx.x * 256 + t;
    int b   = idx >> 14;
    int hw  = idx & (HW_ - 1);

    float acc[18];
#pragma unroll
    for (int j = 0; j < 18; j++) acc[j] = sb[j];

    const float* xp = x + (size_t)b * C_ * HW_ + hw;
#pragma unroll 4
    for (int c = 0; c < 64; c++) {
        float v = __ldg(xp + (size_t)c * HW_);
#pragma unroll
        for (int j = 0; j < 18; j++) acc[j] = fmaf(v, sw[j * 64 + c], acc[j]);
    }
    float* op = g_off + (size_t)b * 18 * HW_ + hw;
#pragma unroll
    for (int j = 0; j < 18; j++) op[(size_t)j * HW_] = acc[j];
}

// ---------------------------------------------------------------------------
// Kernel 3: weights -> bf16 split hi/lo, XOR-swizzled rows [o][c]
// ---------------------------------------------------------------------------
__global__ void k_reorder_w(const float* __restrict__ w) {
    int i = blockIdx.x * 256 + threadIdx.x;          // over 9*64*64
    if (i >= K2_ * O_ * C_) return;
    int c = i & 63;
    int r = i >> 6;
    int o = r & 63;
    int k = r >> 6;
    float v = w[((size_t)o * 64 + c) * 9 + k];
    __nv_bfloat16 hi = __float2bfloat16(v);
    float res = v - __bfloat162float(hi);
    __nv_bfloat16 lo = __float2bfloat16(res);
    int idx = o * 64 + ((((c >> 3) ^ (o & 7)) << 3)) + (c & 7);
    g_wbh[k * 4096 + idx] = hi;
    g_wbl[k * 4096 + idx] = lo;
}

// ---------------------------------------------------------------------------
// Kernel 4: warp-specialized deformable conv.
// 512 threads: warps 0-7 produce (sample A, stage B), warps 8-15 consume
// (ldmatrix + HMMA + epilogue). Double-buffered A/B; named barriers:
//   full[buf]  = id 1+buf : producers arrive, consumers sync
//   empty[buf] = id 3+buf : consumers arrive, producers sync
// ---------------------------------------------------------------------------
#define A_BUF0   0          // hi at +0, lo at +16384  (32KB per buffer)
#define B_BUF0   65536      // hi at +0, lo at +8192   (16KB per buffer)
#define S_OFF    98304
#define SMEM_SZ  (S_OFF + 18 * 128 * 4)

__global__ void __launch_bounds__(512, 1) k_main(float* __restrict__ out) {
    extern __shared__ char smem[];
    uint32_t sbm = smem_u32(smem);
    float* s_off = (float*)(smem + S_OFF);

    int t    = threadIdx.x;
    int lane = t & 31;
    int wid  = t >> 5;
    int h    = blockIdx.x & 127;
    int b    = blockIdx.x >> 7;

    // stage offsets for this row (all threads, coalesced)
    {
        const float* op = g_off + (size_t)b * 18 * HW_ + (size_t)h * W_;
        for (int i = t; i < 18 * 128; i += 512)
            s_off[i] = op[(size_t)(i >> 7) * HW_ + (i & 127)];
    }
    __syncthreads();

    if (wid < 8) {
        // ================= PRODUCER =================
        const int pa_cq = t & 15;    // float4 channel chunk 0..15
        const int pa_p0 = t >> 4;    // pixel within pass (0..15)
        const float* xtb = g_xt + (size_t)b * HW_ * C_;

        for (int k = 0; k < 9; k++) {
            int buf = k & 1;
            if (k >= 2) BAR_SYNC(3 + buf);          // wait consumers freed buf

            char* a_hi = smem + A_BUF0 + buf * 32768;
            char* a_lo = a_hi + 16384;
            char* b_hi = smem + B_BUF0 + buf * 16384;
            char* b_lo = b_hi + 8192;

            // stage B_k hi/lo (pre-swizzled, 8KB each)
            {
                const uint4* sh = (const uint4*)g_wbh + (size_t)k * 512;
                const uint4* sl = (const uint4*)g_wbl + (size_t)k * 512;
                ((uint4*)b_hi)[t]       = __ldg(sh + t);
                ((uint4*)b_hi)[t + 256] = __ldg(sh + t + 256);
                ((uint4*)b_lo)[t]       = __ldg(sl + t);
                ((uint4*)b_lo)[t + 256] = __ldg(sl + t + 256);
            }

            int kh = k / 3;
            int kw = k - kh * 3;

#pragma unroll 2
            for (int pass = 0; pass < 8; pass++) {
                int p = pass * 16 + pa_p0;
                float py = (float)(h - 1 + kh) + s_off[(2 * k) * 128 + p];
                float px = (float)(p - 1 + kw) + s_off[(2 * k + 1) * 128 + p];
                float fy0 = floorf(py), fx0 = floorf(px);
                float wy1 = py - fy0,   wx1 = px - fx0;
                float wy0 = 1.0f - wy1, wx0 = 1.0f - wx1;
                int y0 = (int)fy0, x0 = (int)fx0;
                int y1 = y0 + 1,   x1 = x0 + 1;
                bool vy0 = (unsigned)y0 < (unsigned)H_;
                bool vy1 = (unsigned)y1 < (unsigned)H_;
                bool vx0 = (unsigned)x0 < (unsigned)W_;
                bool vx1 = (unsigned)x1 < (unsigned)W_;
                int y0c = min(max(y0, 0), H_ - 1), y1c = min(max(y1, 0), H_ - 1);
                int x0c = min(max(x0, 0), W_ - 1), x1c = min(max(x1, 0), W_ - 1);
                float w00 = (vy0 && vx0) ? wy0 * wx0 : 0.0f;
                float w01 = (vy0 && vx1) ? wy0 * wx1 : 0.0f;
                float w10 = (vy1 && vx0) ? wy1 * wx0 : 0.0f;
                float w11 = (vy1 && vx1) ? wy1 * wx1 : 0.0f;

                const float4* r00 = (const float4*)(xtb + (size_t)(y0c * W_ + x0c) * C_) + pa_cq;
                const float4* r01 = (const float4*)(xtb + (size_t)(y0c * W_ + x1c) * C_) + pa_cq;
                const float4* r10 = (const float4*)(xtb + (size_t)(y1c * W_ + x0c) * C_) + pa_cq;
                const float4* r11 = (const float4*)(xtb + (size_t)(y1c * W_ + x1c) * C_) + pa_cq;
                float4 va = __ldg(r00);
                float4 vb = __ldg(r01);
                float4 vc = __ldg(r10);
                float4 vd = __ldg(r11);

                float4 s;
                s.x = w00 * va.x + w01 * vb.x + w10 * vc.x + w11 * vd.x;
                s.y = w00 * va.y + w01 * vb.y + w10 * vc.y + w11 * vd.y;
                s.z = w00 * va.z + w01 * vb.z + w10 * vc.z + w11 * vd.z;
                s.w = w00 * va.w + w01 * vb.w + w10 * vc.w + w11 * vd.w;

                uint32_t h0 = cvt2bf(s.y, s.x);
                uint32_t h1 = cvt2bf(s.w, s.z);
                float f0 = __uint_as_float(h0 << 16);
                float f1 = __uint_as_float(h0 & 0xFFFF0000u);
                float f2 = __uint_as_float(h1 << 16);
                float f3 = __uint_as_float(h1 & 0xFFFF0000u);
                uint32_t l0 = cvt2bf(s.y - f1, s.x - f0);
                uint32_t l1 = cvt2bf(s.w - f3, s.z - f2);

                int chunk = (pa_cq >> 1) ^ (p & 7);
                int off   = p * 128 + chunk * 16 + (pa_cq & 1) * 8;
                *(uint2*)(a_hi + off) = make_uint2(h0, h1);
                *(uint2*)(a_lo + off) = make_uint2(l0, l1);
            }
            BAR_ARRIVE(1 + buf);                   // buf full
        }
    } else {
        // ================= CONSUMER =================
        const int cw = wid - 8;
        const int wm = cw & 3;       // px group: 32*wm .. +31
        const int wn = cw >> 2;      // o  group: 32*wn .. +31
        const int a_r  = lane & 15;
        const int a_q  = lane >> 4;
        const int b_or = (lane & 7) + ((lane >> 4) << 3);
        const int b_qb = (lane >> 3) & 1;

        float acc[2][4][4];
#pragma unroll
        for (int mi = 0; mi < 2; mi++)
#pragma unroll
            for (int nt = 0; nt < 4; nt++)
#pragma unroll
                for (int j = 0; j < 4; j++) acc[mi][nt][j] = 0.0f;

        for (int k = 0; k < 9; k++) {
            int buf = k & 1;
            BAR_SYNC(1 + buf);                     // wait buf full

            uint32_t a_hi = sbm + A_BUF0 + buf * 32768;
            uint32_t b_hi = sbm + B_BUF0 + buf * 16384;

#pragma unroll
            for (int kt = 0; kt < 4; kt++) {
                uint32_t ah[2][4], al[2][4];
#pragma unroll
                for (int mi = 0; mi < 2; mi++) {
                    int row = wm * 32 + mi * 16 + a_r;
                    uint32_t ad = a_hi + row * 128 +
                                  (((2 * kt + a_q) ^ (a_r & 7)) * 16);
                    LDMX4(ah[mi], ad);
                    LDMX4(al[mi], ad + 16384);
                }
                uint32_t bh[2][4], bl[2][4];
#pragma unroll
                for (int j = 0; j < 2; j++) {
                    int o = wn * 32 + j * 16 + b_or;
                    uint32_t bd = b_hi + o * 128 +
                                  (((2 * kt + b_qb) ^ (o & 7)) * 16);
                    LDMX4(bh[j], bd);
                    LDMX4(bl[j], bd + 8192);
                }
#pragma unroll
                for (int mi = 0; mi < 2; mi++) {
#pragma unroll
                    for (int nt = 0; nt < 4; nt++) {
                        const uint32_t* bhp = &bh[nt >> 1][(nt & 1) * 2];
                        const uint32_t* blp = &bl[nt >> 1][(nt & 1) * 2];
                        MMA16816(acc[mi][nt], ah[mi], bhp[0], bhp[1]);
                        MMA16816(acc[mi][nt], al[mi], bhp[0], bhp[1]);
                        MMA16816(acc[mi][nt], ah[mi], blp[0], blp[1]);
                    }
                }
            }
            if (k < 7) BAR_ARRIVE(3 + buf);        // buf empty (not needed at end)
        }

        // ---- Epilogue ----
#pragma unroll
        for (int mi = 0; mi < 2; mi++) {
            int px = wm * 32 + mi * 16 + (lane >> 2);
#pragma unroll
            for (int nt = 0; nt < 4; nt++) {
                int o0 = wn * 32 + nt * 8 + 2 * (lane & 3);
                float* ob = out + ((size_t)(b * 64 + o0)) * HW_ + (size_t)h * W_;
                ob[px]           = acc[mi][nt][0];
                ob[HW_ + px]     = acc[mi][nt][1];
                ob[px + 8]       = acc[mi][nt][2];
                ob[HW_ + px + 8] = acc[mi][nt][3];
            }
        }
    }
}

// ---------------------------------------------------------------------------
extern "C" void kernel_launch(void* const* d_in, const int* in_sizes, int n_in,
                              void* d_out, int out_size) {
    const float* x     = (const float*)d_in[0];   // (8,64,128,128)
    const float* wght  = (const float*)d_in[1];   // (64,64,3,3)
    const float* w_off = (const float*)d_in[2];   // (18,64)
    const float* b_off = (const float*)d_in[3];   // (18,)
    float* out = (float*)d_out;                   // (8,64,128,128)

    k_transpose<<<dim3(HW_ / 32, C_ / 32, B_), dim3(32, 8)>>>(x);
    k_offsets<<<(B_ * HW_) / 256, 256>>>(x, w_off, b_off);
    k_reorder_w<<<(K2_ * O_ * C_ + 255) / 256, 256>>>(wght);

    cudaFuncSetAttribute(k_main, cudaFuncAttributeMaxDynamicSharedMemorySize,
                         SMEM_SZ);
    k_main<<<B_ * H_, 512, SMEM_SZ>>>(out);
}

// round 6
// speedup vs baseline: 1.2709x; 1.2709x over previous
#include <cuda_runtime.h>
#include <cuda_bf16.h>
#include <cstdint>

#define B_  8
#define C_  64
#define H_  128
#define W_  128
#define O_  64
#define HW_ (H_*W_)
#define K2_ 9

// Scratch (device globals; no allocation allowed)
__device__ float g_xt[B_*HW_*C_];              // x transposed to [b][h][w][c]
__device__ float g_off[B_*2*K2_*HW_];          // offsets planar [b][j][h][w]
__device__ __nv_bfloat16 g_wbh[K2_*4096];      // weight hi, swizzled [k][o(64) x c(64)]
__device__ __nv_bfloat16 g_wbl[K2_*4096];      // weight lo

// ---------------------------------------------------------------------------
__device__ __forceinline__ uint32_t smem_u32(const void* p) {
    uint32_t a;
    asm("{ .reg .u64 t; cvta.to.shared.u64 t, %1; cvt.u32.u64 %0, t; }"
        : "=r"(a) : "l"(p));
    return a;
}
__device__ __forceinline__ uint32_t cvt2bf(float hi, float lo) {
    uint32_t r;
    asm("cvt.rn.bf16x2.f32 %0, %1, %2;" : "=r"(r) : "f"(hi), "f"(lo));
    return r;
}
#define LDMX4(r, addr)                                                       \
    asm volatile("ldmatrix.sync.aligned.m8n8.x4.shared.b16 {%0,%1,%2,%3}, [%4];" \
        : "=r"((r)[0]), "=r"((r)[1]), "=r"((r)[2]), "=r"((r)[3]) : "r"(addr))
#define MMA16816(d, a, b0, b1)                                               \
    asm volatile("mma.sync.aligned.m16n8k16.row.col.f32.bf16.bf16.f32 "      \
        "{%0,%1,%2,%3}, {%4,%5,%6,%7}, {%8,%9}, {%0,%1,%2,%3};"              \
        : "+f"((d)[0]), "+f"((d)[1]), "+f"((d)[2]), "+f"((d)[3])             \
        : "r"((a)[0]), "r"((a)[1]), "r"((a)[2]), "r"((a)[3]),                \
          "r"(b0), "r"(b1))

// ---------------------------------------------------------------------------
// Kernel 1: NCHW -> NHWC transpose of x
// ---------------------------------------------------------------------------
__global__ void k_transpose(const float* __restrict__ x) {
    __shared__ float tile[32][33];
    int b  = blockIdx.z;
    int c0 = blockIdx.y * 32;
    int p0 = blockIdx.x * 32;
    int tx = threadIdx.x, ty = threadIdx.y;
    const float* xb = x + (size_t)b * C_ * HW_;
#pragma unroll
    for (int i = 0; i < 32; i += 8)
        tile[ty + i][tx] = xb[(size_t)(c0 + ty + i) * HW_ + p0 + tx];
    __syncthreads();
    float* xtb = g_xt + (size_t)b * HW_ * C_;
#pragma unroll
    for (int i = 0; i < 32; i += 8)
        xtb[(size_t)(p0 + ty + i) * C_ + c0 + tx] = tile[tx][ty + i];
}

// ---------------------------------------------------------------------------
// Kernel 2: offsets  off[b,j,h,w] = sum_c x[b,c,h,w] * w_off[j,c] + b_off[j]
// ---------------------------------------------------------------------------
__global__ void k_offsets(const float* __restrict__ x,
                          const float* __restrict__ w_off,
                          const float* __restrict__ b_off) {
    __shared__ float sw[18 * 64];
    __shared__ float sb[18];
    int t = threadIdx.x;
    for (int i = t; i < 18 * 64; i += 256) sw[i] = w_off[i];
    if (t < 18) sb[t] = b_off[t];
    __syncthreads();

    int idx = blockIdx.x * 256 + t;
    int b   = idx >> 14;
    int hw  = idx & (HW_ - 1);

    float acc[18];
#pragma unroll
    for (int j = 0; j < 18; j++) acc[j] = sb[j];

    const float* xp = x + (size_t)b * C_ * HW_ + hw;
#pragma unroll 4
    for (int c = 0; c < 64; c++) {
        float v = __ldg(xp + (size_t)c * HW_);
#pragma unroll
        for (int j = 0; j < 18; j++) acc[j] = fmaf(v, sw[j * 64 + c], acc[j]);
    }
    float* op = g_off + (size_t)b * 18 * HW_ + hw;
#pragma unroll
    for (int j = 0; j < 18; j++) op[(size_t)j * HW_] = acc[j];
}

// ---------------------------------------------------------------------------
// Kernel 3: weights -> bf16 split hi/lo, XOR-swizzled rows [o][c]
// ---------------------------------------------------------------------------
__global__ void k_reorder_w(const float* __restrict__ w) {
    int i = blockIdx.x * 256 + threadIdx.x;          // over 9*64*64
    if (i >= K2_ * O_ * C_) return;
    int c = i & 63;
    int r = i >> 6;
    int o = r & 63;
    int k = r >> 6;
    float v = w[((size_t)o * 64 + c) * 9 + k];
    __nv_bfloat16 hi = __float2bfloat16(v);
    float res = v - __bfloat162float(hi);
    __nv_bfloat16 lo = __float2bfloat16(res);
    int idx = o * 64 + ((((c >> 3) ^ (o & 7)) << 3)) + (c & 7);
    g_wbh[k * 4096 + idx] = hi;
    g_wbl[k * 4096 + idx] = lo;
}

// ---------------------------------------------------------------------------
// Kernel 4: main deformable conv via mma.sync (HMMA bf16, split-2 precision).
// One CTA per (b, h): M=128 px, N=64 o, K=64 c per tap, 9 taps.
// Homogeneous warps, 3 CTAs/SM for latency hiding; B-stage LDGs are
// register-prefetched at tap start and STS'd after sampling.
// ---------------------------------------------------------------------------
#define A_HI   0
#define A_LO   16384
#define B_HI   32768
#define B_LO   40960
#define S_OFF  49152
#define SMEM_SZ (S_OFF + 18 * 128 * 4)

__global__ void __launch_bounds__(256, 3) k_main(float* __restrict__ out) {
    extern __shared__ char smem[];
    uint32_t sb = smem_u32(smem);
    float* s_off = (float*)(smem + S_OFF);

    int t    = threadIdx.x;
    int lane = t & 31;
    int wid  = t >> 5;
    int h    = blockIdx.x & 127;
    int b    = blockIdx.x >> 7;

    // stage offsets for this row (coalesced)
    {
        const float* op = g_off + (size_t)b * 18 * HW_ + (size_t)h * W_;
        for (int i = t; i < 18 * 128; i += 256)
            s_off[i] = op[(size_t)(i >> 7) * HW_ + (i & 127)];
    }

    float acc[2][4][4];
#pragma unroll
    for (int mi = 0; mi < 2; mi++)
#pragma unroll
        for (int nt = 0; nt < 4; nt++)
#pragma unroll
            for (int j = 0; j < 4; j++) acc[mi][nt][j] = 0.0f;

    // Phase-A mapping
    const int pa_cq = t & 15;    // float4 channel chunk 0..15
    const int pa_p0 = t >> 4;    // pixel within pass
    // Warp tile mapping
    const int wm = wid & 3;      // px group: 32*wm .. +31
    const int wn = wid >> 2;     // o  group: 32*wn .. +31
    // ldmatrix lane roles
    const int a_r  = lane & 15;
    const int a_q  = lane >> 4;
    const int b_or = (lane & 7) + ((lane >> 4) << 3);
    const int b_qb = (lane >> 3) & 1;

    const float* xtb = g_xt + (size_t)b * HW_ * C_;

    __syncthreads();

    for (int k = 0; k < 9; k++) {
        // prefetch B_k hi/lo into registers (latency hidden behind sampling)
        uint4 wbh0, wbh1, wbl0, wbl1;
        {
            const uint4* sh = (const uint4*)g_wbh + (size_t)k * 512;
            const uint4* sl = (const uint4*)g_wbl + (size_t)k * 512;
            wbh0 = __ldg(sh + t);
            wbh1 = __ldg(sh + t + 256);
            wbl0 = __ldg(sl + t);
            wbl1 = __ldg(sl + t + 256);
        }

        __syncthreads();   // previous phase-B reads of A/B finished

        int kh = k / 3;
        int kw = k - kh * 3;

        // ---- Phase A: bilinear sampling -> bf16 hi/lo A tile (swizzled) ----
#pragma unroll 2
        for (int pass = 0; pass < 8; pass++) {
            int p = pass * 16 + pa_p0;
            float py = (float)(h - 1 + kh) + s_off[(2 * k) * 128 + p];
            float px = (float)(p - 1 + kw) + s_off[(2 * k + 1) * 128 + p];
            int y0 = __float2int_rd(py);
            int x0 = __float2int_rd(px);
            float wy1 = py - (float)y0, wx1 = px - (float)x0;
            float wy0 = 1.0f - wy1,     wx0 = 1.0f - wx1;
            int y1 = y0 + 1, x1 = x0 + 1;
            bool vy0 = (unsigned)y0 < (unsigned)H_;
            bool vy1 = (unsigned)y1 < (unsigned)H_;
            bool vx0 = (unsigned)x0 < (unsigned)W_;
            bool vx1 = (unsigned)x1 < (unsigned)W_;
            int y0c = min(max(y0, 0), H_ - 1), y1c = min(max(y1, 0), H_ - 1);
            int x0c = min(max(x0, 0), W_ - 1), x1c = min(max(x1, 0), W_ - 1);
            float w00 = (vy0 && vx0) ? wy0 * wx0 : 0.0f;
            float w01 = (vy0 && vx1) ? wy0 * wx1 : 0.0f;
            float w10 = (vy1 && vx0) ? wy1 * wx0 : 0.0f;
            float w11 = (vy1 && vx1) ? wy1 * wx1 : 0.0f;

            const float4* r00 = (const float4*)(xtb + (size_t)(y0c * W_ + x0c) * C_) + pa_cq;
            const float4* r01 = (const float4*)(xtb + (size_t)(y0c * W_ + x1c) * C_) + pa_cq;
            const float4* r10 = (const float4*)(xtb + (size_t)(y1c * W_ + x0c) * C_) + pa_cq;
            const float4* r11 = (const float4*)(xtb + (size_t)(y1c * W_ + x1c) * C_) + pa_cq;
            float4 va = __ldg(r00);
            float4 vb = __ldg(r01);
            float4 vc = __ldg(r10);
            float4 vd = __ldg(r11);

            float4 s;
            s.x = w00 * va.x + w01 * vb.x + w10 * vc.x + w11 * vd.x;
            s.y = w00 * va.y + w01 * vb.y + w10 * vc.y + w11 * vd.y;
            s.z = w00 * va.z + w01 * vb.z + w10 * vc.z + w11 * vd.z;
            s.w = w00 * va.w + w01 * vb.w + w10 * vc.w + w11 * vd.w;

            // split to bf16 hi/lo (low bf16 = lower channel)
            uint32_t h0 = cvt2bf(s.y, s.x);
            uint32_t h1 = cvt2bf(s.w, s.z);
            float f0 = __uint_as_float(h0 << 16);
            float f1 = __uint_as_float(h0 & 0xFFFF0000u);
            float f2 = __uint_as_float(h1 << 16);
            float f3 = __uint_as_float(h1 & 0xFFFF0000u);
            uint32_t l0 = cvt2bf(s.y - f1, s.x - f0);
            uint32_t l1 = cvt2bf(s.w - f3, s.z - f2);

            int chunk = (pa_cq >> 1) ^ (p & 7);
            int off   = p * 128 + chunk * 16 + (pa_cq & 1) * 8;
            *(uint2*)(smem + A_HI + off) = make_uint2(h0, h1);
            *(uint2*)(smem + A_LO + off) = make_uint2(l0, l1);
        }

        // store prefetched B (pre-swizzled layout)
        ((uint4*)(smem + B_HI))[t]       = wbh0;
        ((uint4*)(smem + B_HI))[t + 256] = wbh1;
        ((uint4*)(smem + B_LO))[t]       = wbl0;
        ((uint4*)(smem + B_LO))[t + 256] = wbl1;

        __syncthreads();

        // ---- Phase B: HMMA over 4 k-tiles ----
#pragma unroll
        for (int kt = 0; kt < 4; kt++) {
            uint32_t ah[2][4], al[2][4];
#pragma unroll
            for (int mi = 0; mi < 2; mi++) {
                int row = wm * 32 + mi * 16 + a_r;
                uint32_t ad = sb + A_HI + row * 128 +
                              (((2 * kt + a_q) ^ (a_r & 7)) * 16);
                LDMX4(ah[mi], ad);
                LDMX4(al[mi], ad + (A_LO - A_HI));
            }
            uint32_t bh[2][4], bl[2][4];
#pragma unroll
            for (int j = 0; j < 2; j++) {
                int o = wn * 32 + j * 16 + b_or;
                uint32_t bd = sb + B_HI + o * 128 +
                              (((2 * kt + b_qb) ^ (o & 7)) * 16);
                LDMX4(bh[j], bd);
                LDMX4(bl[j], bd + (B_LO - B_HI));
            }
#pragma unroll
            for (int mi = 0; mi < 2; mi++) {
#pragma unroll
                for (int nt = 0; nt < 4; nt++) {
                    const uint32_t* bhp = &bh[nt >> 1][(nt & 1) * 2];
                    const uint32_t* blp = &bl[nt >> 1][(nt & 1) * 2];
                    MMA16816(acc[mi][nt], ah[mi], bhp[0], bhp[1]);
                    MMA16816(acc[mi][nt], al[mi], bhp[0], bhp[1]);
                    MMA16816(acc[mi][nt], ah[mi], blp[0], blp[1]);
                }
            }
        }
    }

    // ---- Epilogue: direct STG ----
    {
#pragma unroll
        for (int mi = 0; mi < 2; mi++) {
            int px = wm * 32 + mi * 16 + (lane >> 2);
#pragma unroll
            for (int nt = 0; nt < 4; nt++) {
                int o0 = wn * 32 + nt * 8 + 2 * (lane & 3);
                float* ob = out + ((size_t)(b * 64 + o0)) * HW_ + (size_t)h * W_;
                ob[px]           = acc[mi][nt][0];
                ob[HW_ + px]     = acc[mi][nt][1];
                ob[px + 8]       = acc[mi][nt][2];
                ob[HW_ + px + 8] = acc[mi][nt][3];
            }
        }
    }
}

// ---------------------------------------------------------------------------
extern "C" void kernel_launch(void* const* d_in, const int* in_sizes, int n_in,
                              void* d_out, int out_size) {
    const float* x     = (const float*)d_in[0];   // (8,64,128,128)
    const float* wght  = (const float*)d_in[1];   // (64,64,3,3)
    const float* w_off = (const float*)d_in[2];   // (18,64)
    const float* b_off = (const float*)d_in[3];   // (18,)
    float* out = (float*)d_out;                   // (8,64,128,128)

    k_transpose<<<dim3(HW_ / 32, C_ / 32, B_), dim3(32, 8)>>>(x);
    k_offsets<<<(B_ * HW_) / 256, 256>>>(x, w_off, b_off);
    k_reorder_w<<<(K2_ * O_ * C_ + 255) / 256, 256>>>(wght);

    cudaFuncSetAttribute(k_main, cudaFuncAttributeMaxDynamicSharedMemorySize,
                         SMEM_SZ);
    k_main<<<B_ * H_, 256, SMEM_SZ>>>(out);
}

// round 7
// speedup vs baseline: 1.6883x; 1.3284x over previous
#include <cuda_runtime.h>
#include <cuda_bf16.h>
#include <cuda_fp16.h>
#include <cstdint>

#define B_  8
#define C_  64
#define H_  128
#define W_  128
#define O_  64
#define HW_ (H_*W_)
#define K2_ 9

// Scratch (device globals; no allocation allowed)
__device__ float g_xt[B_*HW_*C_];          // x transposed to [b][h][w][c]
__device__ float g_off[B_*2*K2_*HW_];      // offsets planar [b][j][h][w]
__device__ __half g_wf[K2_*4096];          // weight fp16, swizzled [k][o(64) x c(64)]

// ---------------------------------------------------------------------------
__device__ __forceinline__ uint32_t smem_u32(const void* p) {
    uint32_t a;
    asm("{ .reg .u64 t; cvta.to.shared.u64 t, %1; cvt.u32.u64 %0, t; }"
        : "=r"(a) : "l"(p));
    return a;
}
__device__ __forceinline__ uint32_t cvt2h(float hi, float lo) {
    uint32_t r;
    asm("cvt.rn.f16x2.f32 %0, %1, %2;" : "=r"(r) : "f"(hi), "f"(lo));
    return r;
}
#define LDMX4(r, addr)                                                       \
    asm volatile("ldmatrix.sync.aligned.m8n8.x4.shared.b16 {%0,%1,%2,%3}, [%4];" \
        : "=r"((r)[0]), "=r"((r)[1]), "=r"((r)[2]), "=r"((r)[3]) : "r"(addr))
#define MMA16816H(d, a, b0, b1)                                              \
    asm volatile("mma.sync.aligned.m16n8k16.row.col.f32.f16.f16.f32 "        \
        "{%0,%1,%2,%3}, {%4,%5,%6,%7}, {%8,%9}, {%0,%1,%2,%3};"              \
        : "+f"((d)[0]), "+f"((d)[1]), "+f"((d)[2]), "+f"((d)[3])             \
        : "r"((a)[0]), "r"((a)[1]), "r"((a)[2]), "r"((a)[3]),                \
          "r"(b0), "r"(b1))

// ---------------------------------------------------------------------------
// Kernel 1: NCHW -> NHWC transpose of x
// ---------------------------------------------------------------------------
__global__ void k_transpose(const float* __restrict__ x) {
    __shared__ float tile[32][33];
    int b  = blockIdx.z;
    int c0 = blockIdx.y * 32;
    int p0 = blockIdx.x * 32;
    int tx = threadIdx.x, ty = threadIdx.y;
    const float* xb = x + (size_t)b * C_ * HW_;
#pragma unroll
    for (int i = 0; i < 32; i += 8)
        tile[ty + i][tx] = xb[(size_t)(c0 + ty + i) * HW_ + p0 + tx];
    __syncthreads();
    float* xtb = g_xt + (size_t)b * HW_ * C_;
#pragma unroll
    for (int i = 0; i < 32; i += 8)
        xtb[(size_t)(p0 + ty + i) * C_ + c0 + tx] = tile[tx][ty + i];
}

// ---------------------------------------------------------------------------
// Kernel 2: offsets  off[b,j,h,w] = sum_c x[b,c,h,w] * w_off[j,c] + b_off[j]
// ---------------------------------------------------------------------------
__global__ void k_offsets(const float* __restrict__ x,
                          const float* __restrict__ w_off,
                          const float* __restrict__ b_off) {
    __shared__ float sw[18 * 64];
    __shared__ float sb[18];
    int t = threadIdx.x;
    for (int i = t; i < 18 * 64; i += 256) sw[i] = w_off[i];
    if (t < 18) sb[t] = b_off[t];
    __syncthreads();

    int idx = blockIdx.x * 256 + t;
    int b   = idx >> 14;
    int hw  = idx & (HW_ - 1);

    float acc[18];
#pragma unroll
    for (int j = 0; j < 18; j++) acc[j] = sb[j];

    const float* xp = x + (size_t)b * C_ * HW_ + hw;
#pragma unroll 4
    for (int c = 0; c < 64; c++) {
        float v = __ldg(xp + (size_t)c * HW_);
#pragma unroll
        for (int j = 0; j < 18; j++) acc[j] = fmaf(v, sw[j * 64 + c], acc[j]);
    }
    float* op = g_off + (size_t)b * 18 * HW_ + hw;
#pragma unroll
    for (int j = 0; j < 18; j++) op[(size_t)j * HW_] = acc[j];
}

// ---------------------------------------------------------------------------
// Kernel 3: weights -> fp16, XOR-swizzled rows [o][c]
// ---------------------------------------------------------------------------
__global__ void k_reorder_w(const float* __restrict__ w) {
    int i = blockIdx.x * 256 + threadIdx.x;          // over 9*64*64
    if (i >= K2_ * O_ * C_) return;
    int c = i & 63;
    int r = i >> 6;
    int o = r & 63;
    int k = r >> 6;
    float v = w[((size_t)o * 64 + c) * 9 + k];
    int idx = o * 64 + ((((c >> 3) ^ (o & 7)) << 3)) + (c & 7);
    g_wf[k * 4096 + idx] = __float2half_rn(v);
}

// ---------------------------------------------------------------------------
// Kernel 4: main deformable conv via mma.sync (HMMA fp16 single-term).
// One CTA per (b, h): M=128 px, N=64 o, K=64 c per tap, 9 taps.
// Per tap: (1) 128 threads precompute per-pixel bilinear weights + corner
// byte-offsets into smem tables (kills the 16x-redundant geometry math),
// (2) all 256 threads gather + fp16-convert A, (3) HMMA.
// ---------------------------------------------------------------------------
#define A_OFF    0          // A tile fp16: 128 rows x 128B = 16KB
#define BW_OFF   16384      // B tile fp16: 64 rows x 128B = 8KB
#define PW_OFF   24576      // per-pixel weights float4: 128 x 16B = 2KB
#define PA_OFF   26624      // per-pixel corner byte-offsets uint4: 128 x 16B = 2KB
#define SMEM_SZ  28672

__global__ void __launch_bounds__(256, 3) k_main(float* __restrict__ out) {
    extern __shared__ char smem[];
    uint32_t sb = smem_u32(smem);
    float4* s_pw = (float4*)(smem + PW_OFF);
    uint4*  s_pa = (uint4*)(smem + PA_OFF);

    int t    = threadIdx.x;
    int lane = t & 31;
    int wid  = t >> 5;
    int h    = blockIdx.x & 127;
    int b    = blockIdx.x >> 7;

    float acc[2][4][4];
#pragma unroll
    for (int mi = 0; mi < 2; mi++)
#pragma unroll
        for (int nt = 0; nt < 4; nt++)
#pragma unroll
            for (int j = 0; j < 4; j++) acc[mi][nt][j] = 0.0f;

    // Phase-A mapping
    const int pa_cq = t & 15;    // 4-channel chunk 0..15 (16B granules)
    const int pa_p0 = t >> 4;    // pixel within pass
    // Warp tile mapping
    const int wm = wid & 3;      // px group: 32*wm .. +31
    const int wn = wid >> 2;     // o  group: 32*wn .. +31
    // ldmatrix lane roles
    const int a_r  = lane & 15;
    const int a_q  = lane >> 4;
    const int b_or = (lane & 7) + ((lane >> 4) << 3);
    const int b_qb = (lane >> 3) & 1;

    const char* xtb = (const char*)(g_xt + (size_t)b * HW_ * C_);
    const float* offb = g_off + (size_t)b * 18 * HW_ + (size_t)h * W_;

    for (int k = 0; k < 9; k++) {
        // prefetch B_k into registers (latency hidden behind syncs/precompute)
        uint4 wb0, wb1;
        {
            const uint4* sh = (const uint4*)g_wf + (size_t)k * 512;
            wb0 = __ldg(sh + t);
            wb1 = __ldg(sh + t + 256);
        }

        __syncthreads();   // previous tap's phase-B reads of A/B/pw done

        // ---- Precompute: per-pixel bilinear weights + corner offsets ----
        if (t < 128) {
            int p = t;
            int kh = k / 3;
            int kw = k - kh * 3;
            float py = (float)(h - 1 + kh) + __ldg(offb + (size_t)(2 * k) * HW_ + p);
            float px = (float)(p - 1 + kw) + __ldg(offb + (size_t)(2 * k + 1) * HW_ + p);
            int y0 = __float2int_rd(py);
            int x0 = __float2int_rd(px);
            float wy1 = py - (float)y0, wx1 = px - (float)x0;
            float wy0 = 1.0f - wy1,     wx0 = 1.0f - wx1;
            int y1 = y0 + 1, x1 = x0 + 1;
            bool vy0 = (unsigned)y0 < (unsigned)H_;
            bool vy1 = (unsigned)y1 < (unsigned)H_;
            bool vx0 = (unsigned)x0 < (unsigned)W_;
            bool vx1 = (unsigned)x1 < (unsigned)W_;
            int y0c = min(max(y0, 0), H_ - 1), y1c = min(max(y1, 0), H_ - 1);
            int x0c = min(max(x0, 0), W_ - 1), x1c = min(max(x1, 0), W_ - 1);
            float4 w4;
            w4.x = (vy0 && vx0) ? wy0 * wx0 : 0.0f;
            w4.y = (vy0 && vx1) ? wy0 * wx1 : 0.0f;
            w4.z = (vy1 && vx0) ? wy1 * wx0 : 0.0f;
            w4.w = (vy1 && vx1) ? wy1 * wx1 : 0.0f;
            uint4 a4;
            a4.x = (uint32_t)((y0c * W_ + x0c) << 8);   // *64ch*4B
            a4.y = (uint32_t)((y0c * W_ + x1c) << 8);
            a4.z = (uint32_t)((y1c * W_ + x0c) << 8);
            a4.w = (uint32_t)((y1c * W_ + x1c) << 8);
            s_pw[p] = w4;
            s_pa[p] = a4;
        }
        __syncthreads();   // pw/pa tables ready

        // ---- Phase A: gather + bilinear + fp16 convert -> A tile ----
#pragma unroll 4
        for (int pass = 0; pass < 8; pass++) {
            int p = pass * 16 + pa_p0;
            float4 w4 = s_pw[p];
            uint4  a4 = s_pa[p];
            int cb = pa_cq * 16;   // channel-chunk byte offset (4 floats)

            float4 va = __ldg((const float4*)(xtb + a4.x + cb));
            float4 vb = __ldg((const float4*)(xtb + a4.y + cb));
            float4 vc = __ldg((const float4*)(xtb + a4.z + cb));
            float4 vd = __ldg((const float4*)(xtb + a4.w + cb));

            float4 s;
            s.x = w4.x * va.x + w4.y * vb.x + w4.z * vc.x + w4.w * vd.x;
            s.y = w4.x * va.y + w4.y * vb.y + w4.z * vc.y + w4.w * vd.y;
            s.z = w4.x * va.z + w4.y * vb.z + w4.z * vc.z + w4.w * vd.z;
            s.w = w4.x * va.w + w4.y * vb.w + w4.z * vc.w + w4.w * vd.w;

            uint32_t h0 = cvt2h(s.y, s.x);   // low half = lower channel
            uint32_t h1 = cvt2h(s.w, s.z);

            int chunk = (pa_cq >> 1) ^ (p & 7);
            int off   = p * 128 + chunk * 16 + (pa_cq & 1) * 8;
            *(uint2*)(smem + A_OFF + off) = make_uint2(h0, h1);
        }

        // store prefetched B (pre-swizzled layout)
        ((uint4*)(smem + BW_OFF))[t & 255]         = (t < 256) ? wb0 : wb0;
        ((uint4*)(smem + BW_OFF))[t]               = wb0;
        ((uint4*)(smem + BW_OFF))[t + 256]         = wb1;

        __syncthreads();   // A, B ready

        // ---- Phase B: HMMA over 4 k-tiles, single fp16 term ----
#pragma unroll
        for (int kt = 0; kt < 4; kt++) {
            uint32_t af[2][4];
#pragma unroll
            for (int mi = 0; mi < 2; mi++) {
                int row = wm * 32 + mi * 16 + a_r;
                uint32_t ad = sb + A_OFF + row * 128 +
                              (((2 * kt + a_q) ^ (a_r & 7)) * 16);
                LDMX4(af[mi], ad);
            }
            uint32_t bf[2][4];
#pragma unroll
            for (int j = 0; j < 2; j++) {
                int o = wn * 32 + j * 16 + b_or;
                uint32_t bd = sb + BW_OFF + o * 128 +
                              (((2 * kt + b_qb) ^ (o & 7)) * 16);
                LDMX4(bf[j], bd);
            }
#pragma unroll
            for (int mi = 0; mi < 2; mi++) {
#pragma unroll
                for (int nt = 0; nt < 4; nt++) {
                    const uint32_t* bp = &bf[nt >> 1][(nt & 1) * 2];
                    MMA16816H(acc[mi][nt], af[mi], bp[0], bp[1]);
                }
            }
        }
    }

    // ---- Epilogue: direct STG ----
    {
#pragma unroll
        for (int mi = 0; mi < 2; mi++) {
            int px = wm * 32 + mi * 16 + (lane >> 2);
#pragma unroll
            for (int nt = 0; nt < 4; nt++) {
                int o0 = wn * 32 + nt * 8 + 2 * (lane & 3);
                float* ob = out + ((size_t)(b * 64 + o0)) * HW_ + (size_t)h * W_;
                ob[px]           = acc[mi][nt][0];
                ob[HW_ + px]     = acc[mi][nt][1];
                ob[px + 8]       = acc[mi][nt][2];
                ob[HW_ + px + 8] = acc[mi][nt][3];
            }
        }
    }
}

// ---------------------------------------------------------------------------
extern "C" void kernel_launch(void* const* d_in, const int* in_sizes, int n_in,
                              void* d_out, int out_size) {
    const float* x     = (const float*)d_in[0];   // (8,64,128,128)
    const float* wght  = (const float*)d_in[1];   // (64,64,3,3)
    const float* w_off = (const float*)d_in[2];   // (18,64)
    const float* b_off = (const float*)d_in[3];   // (18,)
    float* out = (float*)d_out;                   // (8,64,128,128)

    k_transpose<<<dim3(HW_ / 32, C_ / 32, B_), dim3(32, 8)>>>(x);
    k_offsets<<<(B_ * HW_) / 256, 256>>>(x, w_off, b_off);
    k_reorder_w<<<(K2_ * O_ * C_ + 255) / 256, 256>>>(wght);

    cudaFuncSetAttribute(k_main, cudaFuncAttributeMaxDynamicSharedMemorySize,
                         SMEM_SZ);
    k_main<<<B_ * H_, 256, SMEM_SZ>>>(out);
}

// round 8
// speedup vs baseline: 1.8142x; 1.0746x over previous
#include <cuda_runtime.h>
#include <cuda_bf16.h>
#include <cuda_fp16.h>
#include <cstdint>

#define B_  8
#define C_  64
#define H_  128
#define W_  128
#define O_  64
#define HW_ (H_*W_)
#define K2_ 9

// Scratch (device globals; no allocation allowed)
__device__ float g_xt[B_*HW_*C_];          // x transposed to [b][h][w][c]
__device__ float g_off[B_*2*K2_*HW_];      // offsets planar [b][j][h][w]
__device__ __half g_wf[K2_*4096];          // weight fp16, swizzled [k][o(64) x c(64)]

// ---------------------------------------------------------------------------
__device__ __forceinline__ uint32_t smem_u32(const void* p) {
    uint32_t a;
    asm("{ .reg .u64 t; cvta.to.shared.u64 t, %1; cvt.u32.u64 %0, t; }"
        : "=r"(a) : "l"(p));
    return a;
}
__device__ __forceinline__ uint32_t cvt2h(float hi, float lo) {
    uint32_t r;
    asm("cvt.rn.f16x2.f32 %0, %1, %2;" : "=r"(r) : "f"(hi), "f"(lo));
    return r;
}
#define LDMX4(r, addr)                                                       \
    asm volatile("ldmatrix.sync.aligned.m8n8.x4.shared.b16 {%0,%1,%2,%3}, [%4];" \
        : "=r"((r)[0]), "=r"((r)[1]), "=r"((r)[2]), "=r"((r)[3]) : "r"(addr))
#define MMA16816H(d, a, b0, b1)                                              \
    asm volatile("mma.sync.aligned.m16n8k16.row.col.f32.f16.f16.f32 "        \
        "{%0,%1,%2,%3}, {%4,%5,%6,%7}, {%8,%9}, {%0,%1,%2,%3};"              \
        : "+f"((d)[0]), "+f"((d)[1]), "+f"((d)[2]), "+f"((d)[3])             \
        : "r"((a)[0]), "r"((a)[1]), "r"((a)[2]), "r"((a)[3]),                \
          "r"(b0), "r"(b1))

// ---------------------------------------------------------------------------
// Kernel 1 (fused prep): reads x once per 256-pixel block through smem,
// emits (a) NHWC transpose g_xt and (b) offset maps g_off.
// grid = B*HW/256 = 512, block = 256.
// ---------------------------------------------------------------------------
#define SXP 257   // padded row stride (floats)

__global__ void k_prep(const float* __restrict__ x,
                       const float* __restrict__ w_off,
                       const float* __restrict__ b_off) {
    extern __shared__ float sx[];            // [64][SXP]
    __shared__ float sw[18 * 64];
    __shared__ float sbb[18];

    int t   = threadIdx.x;
    int blk = blockIdx.x;
    int b   = blk >> 6;                      // 64 blocks per batch
    int p0  = (blk & 63) * 256;

    const float* xb = x + (size_t)b * C_ * HW_ + p0;
#pragma unroll 8
    for (int c = 0; c < 64; c++)
        sx[c * SXP + t] = __ldg(xb + (size_t)c * HW_ + t);

    for (int i = t; i < 18 * 64; i += 256) sw[i] = w_off[i];
    if (t < 18) sbb[t] = b_off[t];
    __syncthreads();

    // (a) offsets: thread t owns pixel p0+t
    {
        float acc[18];
#pragma unroll
        for (int j = 0; j < 18; j++) acc[j] = sbb[j];
#pragma unroll 4
        for (int c = 0; c < 64; c++) {
            float v = sx[c * SXP + t];
#pragma unroll
            for (int j = 0; j < 18; j++) acc[j] = fmaf(v, sw[j * 64 + c], acc[j]);
        }
        float* op = g_off + (size_t)b * 18 * HW_ + p0 + t;
#pragma unroll
        for (int j = 0; j < 18; j++) op[(size_t)j * HW_] = acc[j];
    }

    // (b) transpose write: thread (tc = t&63 channel, tp4 = t>>6 pixel phase)
    {
        int tc  = t & 63;
        int tp4 = t >> 6;
        float* xtw = g_xt + ((size_t)b * HW_ + p0) * 64;
#pragma unroll 8
        for (int it = 0; it < 64; it++) {
            int p = it * 4 + tp4;
            xtw[(size_t)p * 64 + tc] = sx[tc * SXP + p];
        }
    }
}

// ---------------------------------------------------------------------------
// Kernel 2: weights -> fp16, XOR-swizzled rows [o][c]
// ---------------------------------------------------------------------------
__global__ void k_reorder_w(const float* __restrict__ w) {
    int i = blockIdx.x * 256 + threadIdx.x;          // over 9*64*64
    if (i >= K2_ * O_ * C_) return;
    int c = i & 63;
    int r = i >> 6;
    int o = r & 63;
    int k = r >> 6;
    float v = w[((size_t)o * 64 + c) * 9 + k];
    int idx = o * 64 + ((((c >> 3) ^ (o & 7)) << 3)) + (c & 7);
    g_wf[k * 4096 + idx] = __float2half_rn(v);
}

// ---------------------------------------------------------------------------
// Kernel 3: main deformable conv via mma.sync (HMMA fp16 single-term).
// 512 threads, 2 CTAs/SM. One CTA per (b, h): M=128 px, N=64 o, 9 taps.
// All 9 taps' bilinear weight/corner tables precomputed ONCE into smem,
// then per tap: sync -> sample A + store B -> sync -> HMMA. 2 syncs/tap.
// Warp tile: 16 px x 32 o (acc = 16 regs/thread), 16 warps cover 128x64.
// ---------------------------------------------------------------------------
#define A_OFF    0          // A tile fp16: 128 rows x 128B = 16KB
#define BW_OFF   16384      // B tile fp16: 64 rows x 128B = 8KB
#define PW_OFF   24576      // tables: weights float4 [9][128] = 18KB
#define PA_OFF   43008      // tables: corner byte-offsets uint4 [9][128] = 18KB
#define SMEM_SZ  61440

__global__ void __launch_bounds__(512, 2) k_main(float* __restrict__ out) {
    extern __shared__ char smem[];
    uint32_t sb = smem_u32(smem);
    float4* s_pw = (float4*)(smem + PW_OFF);
    uint4*  s_pa = (uint4*)(smem + PA_OFF);

    int t    = threadIdx.x;
    int lane = t & 31;
    int wid  = t >> 5;
    int h    = blockIdx.x & 127;
    int b    = blockIdx.x >> 7;

    const char* xtb = (const char*)(g_xt + (size_t)b * HW_ * C_);
    const float* offb = g_off + (size_t)b * 18 * HW_ + (size_t)h * W_;

    // ---- Precompute ALL taps' per-pixel bilinear weights + corner offsets ----
    for (int idx = t; idx < 9 * 128; idx += 512) {
        int k = idx >> 7;
        int p = idx & 127;
        int kh = k / 3;
        int kw = k - kh * 3;
        float py = (float)(h - 1 + kh) + __ldg(offb + (size_t)(2 * k) * HW_ + p);
        float px = (float)(p - 1 + kw) + __ldg(offb + (size_t)(2 * k + 1) * HW_ + p);
        int y0 = __float2int_rd(py);
        int x0 = __float2int_rd(px);
        float wy1 = py - (float)y0, wx1 = px - (float)x0;
        float wy0 = 1.0f - wy1,     wx0 = 1.0f - wx1;
        int y1 = y0 + 1, x1 = x0 + 1;
        bool vy0 = (unsigned)y0 < (unsigned)H_;
        bool vy1 = (unsigned)y1 < (unsigned)H_;
        bool vx0 = (unsigned)x0 < (unsigned)W_;
        bool vx1 = (unsigned)x1 < (unsigned)W_;
        int y0c = min(max(y0, 0), H_ - 1), y1c = min(max(y1, 0), H_ - 1);
        int x0c = min(max(x0, 0), W_ - 1), x1c = min(max(x1, 0), W_ - 1);
        float4 w4;
        w4.x = (vy0 && vx0) ? wy0 * wx0 : 0.0f;
        w4.y = (vy0 && vx1) ? wy0 * wx1 : 0.0f;
        w4.z = (vy1 && vx0) ? wy1 * wx0 : 0.0f;
        w4.w = (vy1 && vx1) ? wy1 * wx1 : 0.0f;
        uint4 a4;
        a4.x = (uint32_t)((y0c * W_ + x0c) << 8);   // *64ch*4B
        a4.y = (uint32_t)((y0c * W_ + x1c) << 8);
        a4.z = (uint32_t)((y1c * W_ + x0c) << 8);
        a4.w = (uint32_t)((y1c * W_ + x1c) << 8);
        s_pw[idx] = w4;
        s_pa[idx] = a4;
    }

    float acc[4][4];
#pragma unroll
    for (int nt = 0; nt < 4; nt++)
#pragma unroll
        for (int j = 0; j < 4; j++) acc[nt][j] = 0.0f;

    // Phase-A mapping
    const int pa_cq = t & 15;    // 4-channel chunk 0..15 (16B granules)
    const int pa_p0 = t >> 4;    // pixel within pass (0..31)
    // Warp tile mapping (16 warps)
    const int wm = wid & 7;      // px group: 16*wm .. +15
    const int wn = wid >> 3;     // o  group: 32*wn .. +31
    // ldmatrix lane roles
    const int a_r  = lane & 15;
    const int a_q  = lane >> 4;
    const int b_or = (lane & 7) + ((lane >> 4) << 3);
    const int b_qb = (lane >> 3) & 1;

    __syncthreads();   // tables ready

    for (int k = 0; k < 9; k++) {
        // prefetch B_k into registers (hidden behind sync/sampling)
        uint4 wb;
        {
            const uint4* sh = (const uint4*)g_wf + (size_t)k * 512;
            wb = __ldg(sh + t);
        }

        if (k > 0) __syncthreads();   // previous tap's MMA reads of A/B done

        // ---- Phase A: gather + bilinear + fp16 convert -> A tile ----
        const float4* pwk = s_pw + k * 128;
        const uint4*  pak = s_pa + k * 128;
#pragma unroll
        for (int pass = 0; pass < 4; pass++) {
            int p = pass * 32 + pa_p0;
            float4 w4 = pwk[p];
            uint4  a4 = pak[p];
            int cb = pa_cq * 16;   // channel-chunk byte offset (4 floats)

            float4 va = __ldg((const float4*)(xtb + a4.x + cb));
            float4 vb = __ldg((const float4*)(xtb + a4.y + cb));
            float4 vc = __ldg((const float4*)(xtb + a4.z + cb));
            float4 vd = __ldg((const float4*)(xtb + a4.w + cb));

            float4 s;
            s.x = w4.x * va.x + w4.y * vb.x + w4.z * vc.x + w4.w * vd.x;
            s.y = w4.x * va.y + w4.y * vb.y + w4.z * vc.y + w4.w * vd.y;
            s.z = w4.x * va.z + w4.y * vb.z + w4.z * vc.z + w4.w * vd.z;
            s.w = w4.x * va.w + w4.y * vb.w + w4.z * vc.w + w4.w * vd.w;

            uint32_t h0 = cvt2h(s.y, s.x);   // low half = lower channel
            uint32_t h1 = cvt2h(s.w, s.z);

            int chunk = (pa_cq >> 1) ^ (p & 7);
            int off   = p * 128 + chunk * 16 + (pa_cq & 1) * 8;
            *(uint2*)(smem + A_OFF + off) = make_uint2(h0, h1);
        }

        // store prefetched B (pre-swizzled layout): 512 threads x 16B = 8KB
        ((uint4*)(smem + BW_OFF))[t] = wb;

        __syncthreads();   // A, B ready

        // ---- Phase B: HMMA over 4 k-tiles, single fp16 term ----
#pragma unroll
        for (int kt = 0; kt < 4; kt++) {
            uint32_t af[4];
            {
                int row = wm * 16 + a_r;
                uint32_t ad = sb + A_OFF + row * 128 +
                              (((2 * kt + a_q) ^ (a_r & 7)) * 16);
                LDMX4(af, ad);
            }
            uint32_t bf[2][4];
#pragma unroll
            for (int j = 0; j < 2; j++) {
                int o = wn * 32 + j * 16 + b_or;
                uint32_t bd = sb + BW_OFF + o * 128 +
                              (((2 * kt + b_qb) ^ (o & 7)) * 16);
                LDMX4(bf[j], bd);
            }
#pragma unroll
            for (int nt = 0; nt < 4; nt++) {
                const uint32_t* bp = &bf[nt >> 1][(nt & 1) * 2];
                MMA16816H(acc[nt], af, bp[0], bp[1]);
            }
        }
    }

    // ---- Epilogue: direct STG ----
    {
        int px = wm * 16 + (lane >> 2);
#pragma unroll
        for (int nt = 0; nt < 4; nt++) {
            int o0 = wn * 32 + nt * 8 + 2 * (lane & 3);
            float* ob = out + ((size_t)(b * 64 + o0)) * HW_ + (size_t)h * W_;
            ob[px]           = acc[nt][0];
            ob[HW_ + px]     = acc[nt][1];
            ob[px + 8]       = acc[nt][2];
            ob[HW_ + px + 8] = acc[nt][3];
        }
    }
}

// ---------------------------------------------------------------------------
extern "C" void kernel_launch(void* const* d_in, const int* in_sizes, int n_in,
                              void* d_out, int out_size) {
    const float* x     = (const float*)d_in[0];   // (8,64,128,128)
    const float* wght  = (const float*)d_in[1];   // (64,64,3,3)
    const float* w_off = (const float*)d_in[2];   // (18,64)
    const float* b_off = (const float*)d_in[3];   // (18,)
    float* out = (float*)d_out;                   // (8,64,128,128)

    cudaFuncSetAttribute(k_prep, cudaFuncAttributeMaxDynamicSharedMemorySize,
                         64 * SXP * (int)sizeof(float));
    k_prep<<<(B_ * HW_) / 256, 256, 64 * SXP * sizeof(float)>>>(x, w_off, b_off);
    k_reorder_w<<<(K2_ * O_ * C_ + 255) / 256, 256>>>(wght);

    cudaFuncSetAttribute(k_main, cudaFuncAttributeMaxDynamicSharedMemorySize,
                         SMEM_SZ);
    k_main<<<B_ * H_, 512, SMEM_SZ>>>(out);
}

// round 9
// speedup vs baseline: 2.1645x; 1.1931x over previous
#include <cuda_runtime.h>
#include <cuda_bf16.h>
#include <cuda_fp16.h>
#include <cstdint>

#define B_  8
#define C_  64
#define H_  128
#define W_  128
#define O_  64
#define HW_ (H_*W_)
#define K2_ 9

// Scratch (device globals; no allocation allowed)
__device__ __half g_xh[B_*HW_*C_];         // x transposed to [b][h][w][c], fp16
__device__ float  g_off[B_*2*K2_*HW_];     // offsets planar [b][j][h][w]
__device__ __half g_wf[K2_*4096];          // weight fp16, swizzled [k][o(64) x c(64)]

// ---------------------------------------------------------------------------
__device__ __forceinline__ uint32_t smem_u32(const void* p) {
    uint32_t a;
    asm("{ .reg .u64 t; cvta.to.shared.u64 t, %1; cvt.u32.u64 %0, t; }"
        : "=r"(a) : "l"(p));
    return a;
}
__device__ __forceinline__ uint32_t cvt2h(float hi, float lo) {
    uint32_t r;
    asm("cvt.rn.f16x2.f32 %0, %1, %2;" : "=r"(r) : "f"(hi), "f"(lo));
    return r;
}
__device__ __forceinline__ float2 h2f2(uint32_t u) {
    __half2 h = *reinterpret_cast<__half2*>(&u);
    return __half22float2(h);
}
#define LDMX4(r, addr)                                                       \
    asm volatile("ldmatrix.sync.aligned.m8n8.x4.shared.b16 {%0,%1,%2,%3}, [%4];" \
        : "=r"((r)[0]), "=r"((r)[1]), "=r"((r)[2]), "=r"((r)[3]) : "r"(addr))
#define MMA16816H(d, a, b0, b1)                                              \
    asm volatile("mma.sync.aligned.m16n8k16.row.col.f32.f16.f16.f32 "        \
        "{%0,%1,%2,%3}, {%4,%5,%6,%7}, {%8,%9}, {%0,%1,%2,%3};"              \
        : "+f"((d)[0]), "+f"((d)[1]), "+f"((d)[2]), "+f"((d)[3])             \
        : "r"((a)[0]), "r"((a)[1]), "r"((a)[2]), "r"((a)[3]),                \
          "r"(b0), "r"(b1))

// ---------------------------------------------------------------------------
// Kernel 1: NCHW fp32 -> NHWC fp16 transpose of x (32x32 tiles)
// ---------------------------------------------------------------------------
__global__ void k_transpose(const float* __restrict__ x) {
    __shared__ float tile[32][33];        // [c_local][p_local]
    int b  = blockIdx.z;
    int c0 = blockIdx.y * 32;
    int p0 = blockIdx.x * 32;
    int tx = threadIdx.x, ty = threadIdx.y;
    const float* xb = x + (size_t)b * C_ * HW_;
#pragma unroll
    for (int i = 0; i < 32; i += 8)
        tile[ty + i][tx] = __ldg(xb + (size_t)(c0 + ty + i) * HW_ + p0 + tx);
    __syncthreads();

    // write 512 half2 values (32 px x 16 channel-pairs), 2 per thread
    char* xout = (char*)g_xh + ((size_t)b * HW_ + p0) * (C_ * 2) + c0 * 2;
    int t2 = ty * 32 + tx;                 // 0..255
#pragma unroll
    for (int q = 0; q < 2; q++) {
        int idx = q * 256 + t2;
        int pl  = idx >> 4;                // 0..31
        int cp  = idx & 15;                // channel pair 0..15
        uint32_t v = cvt2h(tile[2 * cp + 1][pl], tile[2 * cp][pl]);
        *(uint32_t*)(xout + (size_t)pl * (C_ * 2) + cp * 4) = v;
    }
}

// ---------------------------------------------------------------------------
// Kernel 2: offsets  off[b,j,h,w] = sum_c x[b,c,h,w] * w_off[j,c] + b_off[j]
// ---------------------------------------------------------------------------
__global__ void k_offsets(const float* __restrict__ x,
                          const float* __restrict__ w_off,
                          const float* __restrict__ b_off) {
    __shared__ float sw[18 * 64];
    __shared__ float sb[18];
    int t = threadIdx.x;
    for (int i = t; i < 18 * 64; i += 256) sw[i] = w_off[i];
    if (t < 18) sb[t] = b_off[t];
    __syncthreads();

    int idx = blockIdx.x * 256 + t;
    int b   = idx >> 14;
    int hw  = idx & (HW_ - 1);

    float acc[18];
#pragma unroll
    for (int j = 0; j < 18; j++) acc[j] = sb[j];

    const float* xp = x + (size_t)b * C_ * HW_ + hw;
#pragma unroll 4
    for (int c = 0; c < 64; c++) {
        float v = __ldg(xp + (size_t)c * HW_);
#pragma unroll
        for (int j = 0; j < 18; j++) acc[j] = fmaf(v, sw[j * 64 + c], acc[j]);
    }
    float* op = g_off + (size_t)b * 18 * HW_ + hw;
#pragma unroll
    for (int j = 0; j < 18; j++) op[(size_t)j * HW_] = acc[j];
}

// ---------------------------------------------------------------------------
// Kernel 3: weights -> fp16, XOR-swizzled rows [o][c]
// ---------------------------------------------------------------------------
__global__ void k_reorder_w(const float* __restrict__ w) {
    int i = blockIdx.x * 256 + threadIdx.x;          // over 9*64*64
    if (i >= K2_ * O_ * C_) return;
    int c = i & 63;
    int r = i >> 6;
    int o = r & 63;
    int k = r >> 6;
    float v = w[((size_t)o * 64 + c) * 9 + k];
    int idx = o * 64 + ((((c >> 3) ^ (o & 7)) << 3)) + (c & 7);
    g_wf[k * 4096 + idx] = __float2half_rn(v);
}

// ---------------------------------------------------------------------------
// Kernel 4: main deformable conv via mma.sync (HMMA fp16 single-term).
// 512 threads, 2 CTAs/SM. One CTA per (b, h): M=128 px, N=64 o, 9 taps.
// fp16 NHWC source: each thread handles an 8-channel granule (16B), so
// phase A is 2 passes of 64 pixels; gather traffic halved vs fp32 source.
// All 9 taps' bilinear tables precomputed once in smem.
// ---------------------------------------------------------------------------
#define A_OFF    0          // A tile fp16: 128 rows x 128B = 16KB
#define BW_OFF   16384      // B tile fp16: 64 rows x 128B = 8KB
#define PW_OFF   24576      // tables: weights float4 [9][128] = 18KB
#define PA_OFF   43008      // tables: corner byte-offsets uint4 [9][128] = 18KB
#define SMEM_SZ  61440

__global__ void __launch_bounds__(512, 2) k_main(float* __restrict__ out) {
    extern __shared__ char smem[];
    uint32_t sb = smem_u32(smem);
    float4* s_pw = (float4*)(smem + PW_OFF);
    uint4*  s_pa = (uint4*)(smem + PA_OFF);

    int t    = threadIdx.x;
    int lane = t & 31;
    int wid  = t >> 5;
    int h    = blockIdx.x & 127;
    int b    = blockIdx.x >> 7;

    const char* xtb = (const char*)(g_xh + (size_t)b * HW_ * C_);
    const float* offb = g_off + (size_t)b * 18 * HW_ + (size_t)h * W_;

    // ---- Precompute ALL taps' per-pixel bilinear weights + corner offsets ----
    for (int idx = t; idx < 9 * 128; idx += 512) {
        int k = idx >> 7;
        int p = idx & 127;
        int kh = k / 3;
        int kw = k - kh * 3;
        float py = (float)(h - 1 + kh) + __ldg(offb + (size_t)(2 * k) * HW_ + p);
        float px = (float)(p - 1 + kw) + __ldg(offb + (size_t)(2 * k + 1) * HW_ + p);
        int y0 = __float2int_rd(py);
        int x0 = __float2int_rd(px);
        float wy1 = py - (float)y0, wx1 = px - (float)x0;
        float wy0 = 1.0f - wy1,     wx0 = 1.0f - wx1;
        int y1 = y0 + 1, x1 = x0 + 1;
        bool vy0 = (unsigned)y0 < (unsigned)H_;
        bool vy1 = (unsigned)y1 < (unsigned)H_;
        bool vx0 = (unsigned)x0 < (unsigned)W_;
        bool vx1 = (unsigned)x1 < (unsigned)W_;
        int y0c = min(max(y0, 0), H_ - 1), y1c = min(max(y1, 0), H_ - 1);
        int x0c = min(max(x0, 0), W_ - 1), x1c = min(max(x1, 0), W_ - 1);
        float4 w4;
        w4.x = (vy0 && vx0) ? wy0 * wx0 : 0.0f;
        w4.y = (vy0 && vx1) ? wy0 * wx1 : 0.0f;
        w4.z = (vy1 && vx0) ? wy1 * wx0 : 0.0f;
        w4.w = (vy1 && vx1) ? wy1 * wx1 : 0.0f;
        uint4 a4;
        a4.x = (uint32_t)((y0c * W_ + x0c) << 7);   // *64ch*2B
        a4.y = (uint32_t)((y0c * W_ + x1c) << 7);
        a4.z = (uint32_t)((y1c * W_ + x0c) << 7);
        a4.w = (uint32_t)((y1c * W_ + x1c) << 7);
        s_pw[idx] = w4;
        s_pa[idx] = a4;
    }

    float acc[4][4];
#pragma unroll
    for (int nt = 0; nt < 4; nt++)
#pragma unroll
        for (int j = 0; j < 4; j++) acc[nt][j] = 0.0f;

    // Phase-A mapping: 8-channel granule per thread
    const int pa_cg = t & 7;     // granule 0..7 (16B of fp16 = 8 channels)
    const int pa_p0 = t >> 3;    // pixel within pass (0..63)
    // Warp tile mapping (16 warps)
    const int wm = wid & 7;      // px group: 16*wm .. +15
    const int wn = wid >> 3;     // o  group: 32*wn .. +31
    // ldmatrix lane roles
    const int a_r  = lane & 15;
    const int a_q  = lane >> 4;
    const int b_or = (lane & 7) + ((lane >> 4) << 3);
    const int b_qb = (lane >> 3) & 1;

    __syncthreads();   // tables ready

    for (int k = 0; k < 9; k++) {
        // prefetch B_k into registers (hidden behind sync/sampling)
        uint4 wb;
        {
            const uint4* sh = (const uint4*)g_wf + (size_t)k * 512;
            wb = __ldg(sh + t);
        }

        if (k > 0) __syncthreads();   // previous tap's MMA reads of A/B done

        // ---- Phase A: fp16 gather + fp32 bilinear -> fp16 A tile ----
        const float4* pwk = s_pw + k * 128;
        const uint4*  pak = s_pa + k * 128;
#pragma unroll
        for (int pass = 0; pass < 2; pass++) {
            int p = pass * 64 + pa_p0;
            float4 w4 = pwk[p];
            uint4  a4 = pak[p];
            int cb = pa_cg * 16;   // granule byte offset (8 fp16 channels)

            uint4 u0 = __ldg((const uint4*)(xtb + a4.x + cb));
            uint4 u1 = __ldg((const uint4*)(xtb + a4.y + cb));
            uint4 u2 = __ldg((const uint4*)(xtb + a4.z + cb));
            uint4 u3 = __ldg((const uint4*)(xtb + a4.w + cb));

            uint32_t c0a[4] = {u0.x, u0.y, u0.z, u0.w};
            uint32_t c1a[4] = {u1.x, u1.y, u1.z, u1.w};
            uint32_t c2a[4] = {u2.x, u2.y, u2.z, u2.w};
            uint32_t c3a[4] = {u3.x, u3.y, u3.z, u3.w};

            float2 s[4];
#pragma unroll
            for (int j = 0; j < 4; j++) {
                float2 f = h2f2(c0a[j]);
                s[j].x = w4.x * f.x;
                s[j].y = w4.x * f.y;
            }
#pragma unroll
            for (int j = 0; j < 4; j++) {
                float2 f = h2f2(c1a[j]);
                s[j].x = fmaf(w4.y, f.x, s[j].x);
                s[j].y = fmaf(w4.y, f.y, s[j].y);
            }
#pragma unroll
            for (int j = 0; j < 4; j++) {
                float2 f = h2f2(c2a[j]);
                s[j].x = fmaf(w4.z, f.x, s[j].x);
                s[j].y = fmaf(w4.z, f.y, s[j].y);
            }
#pragma unroll
            for (int j = 0; j < 4; j++) {
                float2 f = h2f2(c3a[j]);
                s[j].x = fmaf(w4.w, f.x, s[j].x);
                s[j].y = fmaf(w4.w, f.y, s[j].y);
            }

            uint4 o;
            o.x = cvt2h(s[0].y, s[0].x);   // low half = lower channel
            o.y = cvt2h(s[1].y, s[1].x);
            o.z = cvt2h(s[2].y, s[2].x);
            o.w = cvt2h(s[3].y, s[3].x);

            int chunk = pa_cg ^ (p & 7);
            *(uint4*)(smem + A_OFF + p * 128 + chunk * 16) = o;
        }

        // store prefetched B (pre-swizzled layout): 512 threads x 16B = 8KB
        ((uint4*)(smem + BW_OFF))[t] = wb;

        __syncthreads();   // A, B ready

        // ---- Phase B: HMMA over 4 k-tiles, single fp16 term ----
#pragma unroll
        for (int kt = 0; kt < 4; kt++) {
            uint32_t af[4];
            {
                int row = wm * 16 + a_r;
                uint32_t ad = sb + A_OFF + row * 128 +
                              (((2 * kt + a_q) ^ (a_r & 7)) * 16);
                LDMX4(af, ad);
            }
            uint32_t bf[2][4];
#pragma unroll
            for (int j = 0; j < 2; j++) {
                int o = wn * 32 + j * 16 + b_or;
                uint32_t bd = sb + BW_OFF + o * 128 +
                              (((2 * kt + b_qb) ^ (o & 7)) * 16);
                LDMX4(bf[j], bd);
            }
#pragma unroll
            for (int nt = 0; nt < 4; nt++) {
                const uint32_t* bp = &bf[nt >> 1][(nt & 1) * 2];
                MMA16816H(acc[nt], af, bp[0], bp[1]);
            }
        }
    }

    // ---- Epilogue: direct STG ----
    {
        int px = wm * 16 + (lane >> 2);
#pragma unroll
        for (int nt = 0; nt < 4; nt++) {
            int o0 = wn * 32 + nt * 8 + 2 * (lane & 3);
            float* ob = out + ((size_t)(b * 64 + o0)) * HW_ + (size_t)h * W_;
            ob[px]           = acc[nt][0];
            ob[HW_ + px]     = acc[nt][1];
            ob[px + 8]       = acc[nt][2];
            ob[HW_ + px + 8] = acc[nt][3];
        }
    }
}

// ---------------------------------------------------------------------------
extern "C" void kernel_launch(void* const* d_in, const int* in_sizes, int n_in,
                              void* d_out, int out_size) {
    const float* x     = (const float*)d_in[0];   // (8,64,128,128)
    const float* wght  = (const float*)d_in[1];   // (64,64,3,3)
    const float* w_off = (const float*)d_in[2];   // (18,64)
    const float* b_off = (const float*)d_in[3];   // (18,)
    float* out = (float*)d_out;                   // (8,64,128,128)

    k_transpose<<<dim3(HW_ / 32, C_ / 32, B_), dim3(32, 8)>>>(x);
    k_offsets<<<(B_ * HW_) / 256, 256>>>(x, w_off, b_off);
    k_reorder_w<<<(K2_ * O_ * C_ + 255) / 256, 256>>>(wght);

    cudaFuncSetAttribute(k_main, cudaFuncAttributeMaxDynamicSharedMemorySize,
                         SMEM_SZ);
    k_main<<<B_ * H_, 512, SMEM_SZ>>>(out);
}

// round 10
// speedup vs baseline: 2.3070x; 1.0659x over previous
#include <cuda_runtime.h>
#include <cuda_bf16.h>
#include <cuda_fp16.h>
#include <cstdint>

#define B_  8
#define C_  64
#define H_  128
#define W_  128
#define O_  64
#define HW_ (H_*W_)
#define K2_ 9

// Scratch (device globals; no allocation allowed)
__device__ __half g_xh[B_*HW_*C_];         // x transposed to [b][h][w][c], fp16
__device__ float  g_off[B_*2*K2_*HW_];     // offsets planar [b][j][h][w]
__device__ __half g_wf[K2_*4096];          // weight fp16, swizzled [k][o(64) x c(64)]

// ---------------------------------------------------------------------------
__device__ __forceinline__ uint32_t smem_u32(const void* p) {
    uint32_t a;
    asm("{ .reg .u64 t; cvta.to.shared.u64 t, %1; cvt.u32.u64 %0, t; }"
        : "=r"(a) : "l"(p));
    return a;
}
__device__ __forceinline__ uint32_t cvt2h(float hi, float lo) {
    uint32_t r;
    asm("cvt.rn.f16x2.f32 %0, %1, %2;" : "=r"(r) : "f"(hi), "f"(lo));
    return r;
}
__device__ __forceinline__ float2 h2f2(uint32_t u) {
    __half2 h = *reinterpret_cast<__half2*>(&u);
    return __half22float2(h);
}
#define LDMX4(r, addr)                                                       \
    asm volatile("ldmatrix.sync.aligned.m8n8.x4.shared.b16 {%0,%1,%2,%3}, [%4];" \
        : "=r"((r)[0]), "=r"((r)[1]), "=r"((r)[2]), "=r"((r)[3]) : "r"(addr))
#define MMA16816H(d, a, b0, b1)                                              \
    asm volatile("mma.sync.aligned.m16n8k16.row.col.f32.f16.f16.f32 "        \
        "{%0,%1,%2,%3}, {%4,%5,%6,%7}, {%8,%9}, {%0,%1,%2,%3};"              \
        : "+f"((d)[0]), "+f"((d)[1]), "+f"((d)[2]), "+f"((d)[3])             \
        : "r"((a)[0]), "r"((a)[1]), "r"((a)[2]), "r"((a)[3]),                \
          "r"(b0), "r"(b1))

// ---------------------------------------------------------------------------
// Kernel 1 (lean fused prep): 64px x 64ch tile through smem; one read of x
// produces (a) offset maps g_off and (b) fp16 NHWC transpose g_xh.
// grid = B*HW/64 = 2048, block = 256, smem ~21KB static.
// ---------------------------------------------------------------------------
__global__ void __launch_bounds__(256) k_prep(const float* __restrict__ x,
                                              const float* __restrict__ w_off,
                                              const float* __restrict__ b_off) {
    __shared__ float sx[64][65];          // [c][px]
    __shared__ float sw[18 * 64];
    __shared__ float sbb[18];

    int t   = threadIdx.x;
    int blk = blockIdx.x;                 // 0..2047
    int b   = blk >> 8;                   // 256 blocks per batch
    int p0  = (blk & 255) * 64;

    int px = t & 63;
    int g  = t >> 6;                      // 0..3

    const float* xb = x + (size_t)b * C_ * HW_ + p0;
#pragma unroll
    for (int c = 0; c < 64; c += 4)
        sx[c + g][px] = __ldg(xb + (size_t)(c + g) * HW_ + px);

    for (int i = t; i < 18 * 64; i += 256) sw[i] = w_off[i];
    if (t < 18) sbb[t] = b_off[t];
    __syncthreads();

    // (a) offsets: thread (px, g) computes j = g + 4*i  (i = 0..4, j < 18)
    {
        float acc[5];
#pragma unroll
        for (int i = 0; i < 5; i++) {
            int j = g + 4 * i;
            acc[i] = (j < 18) ? sbb[j] : 0.0f;
        }
#pragma unroll 4
        for (int c = 0; c < 64; c++) {
            float v = sx[c][px];
#pragma unroll
            for (int i = 0; i < 5; i++) {
                int j = g + 4 * i;
                if (j < 18) acc[i] = fmaf(v, sw[j * 64 + c], acc[i]);
            }
        }
        float* op = g_off + (size_t)b * 18 * HW_ + p0 + px;
#pragma unroll
        for (int i = 0; i < 5; i++) {
            int j = g + 4 * i;
            if (j < 18) op[(size_t)j * HW_] = acc[i];
        }
    }

    // (b) transpose write fp16 NHWC: thread (pxw = t>>2, cq = t&3 -> 16 ch)
    {
        int pxw = t >> 2;
        int cq  = t & 3;
        uint32_t v[8];
#pragma unroll
        for (int i = 0; i < 8; i++) {
            int c = cq * 16 + i * 2;
            v[i] = cvt2h(sx[c + 1][pxw], sx[c][pxw]);
        }
        char* xout = (char*)g_xh + ((size_t)b * HW_ + p0 + pxw) * 128 + cq * 32;
        *(uint4*)(xout)      = make_uint4(v[0], v[1], v[2], v[3]);
        *(uint4*)(xout + 16) = make_uint4(v[4], v[5], v[6], v[7]);
    }
}

// ---------------------------------------------------------------------------
// Kernel 2: weights -> fp16, XOR-swizzled rows [o][c]
// ---------------------------------------------------------------------------
__global__ void k_reorder_w(const float* __restrict__ w) {
    int i = blockIdx.x * 256 + threadIdx.x;          // over 9*64*64
    if (i >= K2_ * O_ * C_) return;
    int c = i & 63;
    int r = i >> 6;
    int o = r & 63;
    int k = r >> 6;
    float v = w[((size_t)o * 64 + c) * 9 + k];
    int idx = o * 64 + ((((c >> 3) ^ (o & 7)) << 3)) + (c & 7);
    g_wf[k * 4096 + idx] = __float2half_rn(v);
}

// ---------------------------------------------------------------------------
// Kernel 3: main deformable conv via mma.sync (HMMA fp16 single-term).
// 512 threads, 2 CTAs/SM. One CTA per (b, h): M=128 px, N=64 o, 9 taps.
// Double-buffered A/B -> ONE __syncthreads per tap:
//   sample(k) writes buf k&1; its previous reader was mma(k-2), which every
//   thread finished before passing sync(k-1) (program order), so no extra
//   barrier is needed before overwriting.
// All 9 taps' bilinear tables precomputed once in smem.
// ---------------------------------------------------------------------------
#define A0_OFF   0          // A tile fp16 buf0: 16KB
#define A1_OFF   16384      // A tile fp16 buf1: 16KB
#define B0_OFF   32768      // B buf0: 8KB
#define B1_OFF   40960      // B buf1: 8KB
#define PW_OFF   49152      // tables: weights float4 [9][128] = 18KB
#define PA_OFF   67584      // tables: corner byte-offsets uint4 [9][128] = 18KB
#define SMEM_SZ  86016

__global__ void __launch_bounds__(512, 2) k_main(float* __restrict__ out) {
    extern __shared__ char smem[];
    uint32_t sb = smem_u32(smem);
    float4* s_pw = (float4*)(smem + PW_OFF);
    uint4*  s_pa = (uint4*)(smem + PA_OFF);

    int t    = threadIdx.x;
    int lane = t & 31;
    int wid  = t >> 5;
    int h    = blockIdx.x & 127;
    int b    = blockIdx.x >> 7;

    const char* xtb = (const char*)(g_xh + (size_t)b * HW_ * C_);
    const float* offb = g_off + (size_t)b * 18 * HW_ + (size_t)h * W_;

    // ---- Precompute ALL taps' per-pixel bilinear weights + corner offsets ----
    for (int idx = t; idx < 9 * 128; idx += 512) {
        int k = idx >> 7;
        int p = idx & 127;
        int kh = k / 3;
        int kw = k - kh * 3;
        float py = (float)(h - 1 + kh) + __ldg(offb + (size_t)(2 * k) * HW_ + p);
        float px = (float)(p - 1 + kw) + __ldg(offb + (size_t)(2 * k + 1) * HW_ + p);
        int y0 = __float2int_rd(py);
        int x0 = __float2int_rd(px);
        float wy1 = py - (float)y0, wx1 = px - (float)x0;
        float wy0 = 1.0f - wy1,     wx0 = 1.0f - wx1;
        int y1 = y0 + 1, x1 = x0 + 1;
        bool vy0 = (unsigned)y0 < (unsigned)H_;
        bool vy1 = (unsigned)y1 < (unsigned)H_;
        bool vx0 = (unsigned)x0 < (unsigned)W_;
        bool vx1 = (unsigned)x1 < (unsigned)W_;
        int y0c = min(max(y0, 0), H_ - 1), y1c = min(max(y1, 0), H_ - 1);
        int x0c = min(max(x0, 0), W_ - 1), x1c = min(max(x1, 0), W_ - 1);
        float4 w4;
        w4.x = (vy0 && vx0) ? wy0 * wx0 : 0.0f;
        w4.y = (vy0 && vx1) ? wy0 * wx1 : 0.0f;
        w4.z = (vy1 && vx0) ? wy1 * wx0 : 0.0f;
        w4.w = (vy1 && vx1) ? wy1 * wx1 : 0.0f;
        uint4 a4;
        a4.x = (uint32_t)((y0c * W_ + x0c) << 7);   // *64ch*2B
        a4.y = (uint32_t)((y0c * W_ + x1c) << 7);
        a4.z = (uint32_t)((y1c * W_ + x0c) << 7);
        a4.w = (uint32_t)((y1c * W_ + x1c) << 7);
        s_pw[idx] = w4;
        s_pa[idx] = a4;
    }

    float acc[4][4];
#pragma unroll
    for (int nt = 0; nt < 4; nt++)
#pragma unroll
        for (int j = 0; j < 4; j++) acc[nt][j] = 0.0f;

    // Phase-A mapping: 8-channel granule per thread
    const int pa_cg = t & 7;     // granule 0..7 (16B of fp16 = 8 channels)
    const int pa_p0 = t >> 3;    // pixel within pass (0..63)
    // Warp tile mapping (16 warps)
    const int wm = wid & 7;      // px group: 16*wm .. +15
    const int wn = wid >> 3;     // o  group: 32*wn .. +31
    // ldmatrix lane roles
    const int a_r  = lane & 15;
    const int a_q  = lane >> 4;
    const int b_or = (lane & 7) + ((lane >> 4) << 3);
    const int b_qb = (lane >> 3) & 1;

    __syncthreads();   // tables ready

    for (int k = 0; k < 9; k++) {
        const int buf = k & 1;
        char* a_buf = smem + (buf ? A1_OFF : A0_OFF);
        char* b_buf = smem + (buf ? B1_OFF : B0_OFF);

        // prefetch B_k into registers (hidden behind sampling)
        uint4 wb;
        {
            const uint4* sh = (const uint4*)g_wf + (size_t)k * 512;
            wb = __ldg(sh + t);
        }

        // ---- Phase A: fp16 gather + fp32 bilinear -> fp16 A tile (buf) ----
        const float4* pwk = s_pw + k * 128;
        const uint4*  pak = s_pa + k * 128;
#pragma unroll
        for (int pass = 0; pass < 2; pass++) {
            int p = pass * 64 + pa_p0;
            float4 w4 = pwk[p];
            uint4  a4 = pak[p];
            int cb = pa_cg * 16;   // granule byte offset (8 fp16 channels)

            uint4 u0 = __ldg((const uint4*)(xtb + a4.x + cb));
            uint4 u1 = __ldg((const uint4*)(xtb + a4.y + cb));
            uint4 u2 = __ldg((const uint4*)(xtb + a4.z + cb));
            uint4 u3 = __ldg((const uint4*)(xtb + a4.w + cb));

            uint32_t c0a[4] = {u0.x, u0.y, u0.z, u0.w};
            uint32_t c1a[4] = {u1.x, u1.y, u1.z, u1.w};
            uint32_t c2a[4] = {u2.x, u2.y, u2.z, u2.w};
            uint32_t c3a[4] = {u3.x, u3.y, u3.z, u3.w};

            float2 s[4];
#pragma unroll
            for (int j = 0; j < 4; j++) {
                float2 f = h2f2(c0a[j]);
                s[j].x = w4.x * f.x;
                s[j].y = w4.x * f.y;
            }
#pragma unroll
            for (int j = 0; j < 4; j++) {
                float2 f = h2f2(c1a[j]);
                s[j].x = fmaf(w4.y, f.x, s[j].x);
                s[j].y = fmaf(w4.y, f.y, s[j].y);
            }
#pragma unroll
            for (int j = 0; j < 4; j++) {
                float2 f = h2f2(c2a[j]);
                s[j].x = fmaf(w4.z, f.x, s[j].x);
                s[j].y = fmaf(w4.z, f.y, s[j].y);
            }
#pragma unroll
            for (int j = 0; j < 4; j++) {
                float2 f = h2f2(c3a[j]);
                s[j].x = fmaf(w4.w, f.x, s[j].x);
                s[j].y = fmaf(w4.w, f.y, s[j].y);
            }

            uint4 o;
            o.x = cvt2h(s[0].y, s[0].x);   // low half = lower channel
            o.y = cvt2h(s[1].y, s[1].x);
            o.z = cvt2h(s[2].y, s[2].x);
            o.w = cvt2h(s[3].y, s[3].x);

            int chunk = pa_cg ^ (p & 7);
            *(uint4*)(a_buf + p * 128 + chunk * 16) = o;
        }

        // store prefetched B (pre-swizzled layout): 512 threads x 16B = 8KB
        ((uint4*)b_buf)[t] = wb;

        __syncthreads();   // A(k), B(k) ready; also releases buf for k+2's writes

        // ---- Phase B: HMMA over 4 k-tiles, single fp16 term ----
        uint32_t a_base = sb + (buf ? A1_OFF : A0_OFF);
        uint32_t b_base = sb + (buf ? B1_OFF : B0_OFF);
#pragma unroll
        for (int kt = 0; kt < 4; kt++) {
            uint32_t af[4];
            {
                int row = wm * 16 + a_r;
                uint32_t ad = a_base + row * 128 +
                              (((2 * kt + a_q) ^ (a_r & 7)) * 16);
                LDMX4(af, ad);
            }
            uint32_t bf[2][4];
#pragma unroll
            for (int j = 0; j < 2; j++) {
                int o = wn * 32 + j * 16 + b_or;
                uint32_t bd = b_base + o * 128 +
                              (((2 * kt + b_qb) ^ (o & 7)) * 16);
                LDMX4(bf[j], bd);
            }
#pragma unroll
            for (int nt = 0; nt < 4; nt++) {
                const uint32_t* bp = &bf[nt >> 1][(nt & 1) * 2];
                MMA16816H(acc[nt], af, bp[0], bp[1]);
            }
        }
    }

    // ---- Epilogue: direct STG ----
    {
        int px = wm * 16 + (lane >> 2);
#pragma unroll
        for (int nt = 0; nt < 4; nt++) {
            int o0 = wn * 32 + nt * 8 + 2 * (lane & 3);
            float* ob = out + ((size_t)(b * 64 + o0)) * HW_ + (size_t)h * W_;
            ob[px]           = acc[nt][0];
            ob[HW_ + px]     = acc[nt][1];
            ob[px + 8]       = acc[nt][2];
            ob[HW_ + px + 8] = acc[nt][3];
        }
    }
}

// ---------------------------------------------------------------------------
extern "C" void kernel_launch(void* const* d_in, const int* in_sizes, int n_in,
                              void* d_out, int out_size) {
    const float* x     = (const float*)d_in[0];   // (8,64,128,128)
    const float* wght  = (const float*)d_in[1];   // (64,64,3,3)
    const float* w_off = (const float*)d_in[2];   // (18,64)
    const float* b_off = (const float*)d_in[3];   // (18,)
    float* out = (float*)d_out;                   // (8,64,128,128)

    k_prep<<<B_ * HW_ / 64, 256>>>(x, w_off, b_off);
    k_reorder_w<<<(K2_ * O_ * C_ + 255) / 256, 256>>>(wght);

    cudaFuncSetAttribute(k_main, cudaFuncAttributeMaxDynamicSharedMemorySize,
                         SMEM_SZ);
    k_main<<<B_ * H_, 512, SMEM_SZ>>>(out);
}

// round 11
// speedup vs baseline: 2.3091x; 1.0009x over previous
#include <cuda_runtime.h>
#include <cuda_bf16.h>
#include <cuda_fp16.h>
#include <cstdint>

#define B_  8
#define C_  64
#define H_  128
#define W_  128
#define O_  64
#define HW_ (H_*W_)
#define K2_ 9

// Scratch (device globals; no allocation allowed)
__device__ __half g_xh[B_*HW_*C_];         // x transposed to [b][h][w][c], fp16
__device__ __half g_wf[K2_*4096];          // weight fp16, swizzled [k][o(64) x c(64)]

// ---------------------------------------------------------------------------
__device__ __forceinline__ uint32_t smem_u32(const void* p) {
    uint32_t a;
    asm("{ .reg .u64 t; cvta.to.shared.u64 t, %1; cvt.u32.u64 %0, t; }"
        : "=r"(a) : "l"(p));
    return a;
}
__device__ __forceinline__ uint32_t cvt2h(float hi, float lo) {
    uint32_t r;
    asm("cvt.rn.f16x2.f32 %0, %1, %2;" : "=r"(r) : "f"(hi), "f"(lo));
    return r;
}
__device__ __forceinline__ float2 h2f2(uint32_t u) {
    __half2 h = *reinterpret_cast<__half2*>(&u);
    return __half22float2(h);
}
#define LDMX4(r, addr)                                                       \
    asm volatile("ldmatrix.sync.aligned.m8n8.x4.shared.b16 {%0,%1,%2,%3}, [%4];" \
        : "=r"((r)[0]), "=r"((r)[1]), "=r"((r)[2]), "=r"((r)[3]) : "r"(addr))
#define MMA16816H(d, a, b0, b1)                                              \
    asm volatile("mma.sync.aligned.m16n8k16.row.col.f32.f16.f16.f32 "        \
        "{%0,%1,%2,%3}, {%4,%5,%6,%7}, {%8,%9}, {%0,%1,%2,%3};"              \
        : "+f"((d)[0]), "+f"((d)[1]), "+f"((d)[2]), "+f"((d)[3])             \
        : "r"((a)[0]), "r"((a)[1]), "r"((a)[2]), "r"((a)[3]),                \
          "r"(b0), "r"(b1))

// ---------------------------------------------------------------------------
// Kernel 1: NCHW fp32 -> NHWC fp16 transpose of x (32x32 tiles)
// ---------------------------------------------------------------------------
__global__ void k_transpose(const float* __restrict__ x) {
    __shared__ float tile[32][33];        // [c_local][p_local]
    int b  = blockIdx.z;
    int c0 = blockIdx.y * 32;
    int p0 = blockIdx.x * 32;
    int tx = threadIdx.x, ty = threadIdx.y;
    const float* xb = x + (size_t)b * C_ * HW_;
#pragma unroll
    for (int i = 0; i < 32; i += 8)
        tile[ty + i][tx] = __ldg(xb + (size_t)(c0 + ty + i) * HW_ + p0 + tx);
    __syncthreads();

    // write 512 half2 values (32 px x 16 channel-pairs), 2 per thread
    char* xout = (char*)g_xh + ((size_t)b * HW_ + p0) * (C_ * 2) + c0 * 2;
    int t2 = ty * 32 + tx;                 // 0..255
#pragma unroll
    for (int q = 0; q < 2; q++) {
        int idx = q * 256 + t2;
        int pl  = idx >> 4;                // 0..31
        int cp  = idx & 15;                // channel pair 0..15
        uint32_t v = cvt2h(tile[2 * cp + 1][pl], tile[2 * cp][pl]);
        *(uint32_t*)(xout + (size_t)pl * (C_ * 2) + cp * 4) = v;
    }
}

// ---------------------------------------------------------------------------
// Kernel 2: weights -> fp16, XOR-swizzled rows [o][c]
// ---------------------------------------------------------------------------
__global__ void k_reorder_w(const float* __restrict__ w) {
    int i = blockIdx.x * 256 + threadIdx.x;          // over 9*64*64
    if (i >= K2_ * O_ * C_) return;
    int c = i & 63;
    int r = i >> 6;
    int o = r & 63;
    int k = r >> 6;
    float v = w[((size_t)o * 64 + c) * 9 + k];
    int idx = o * 64 + ((((c >> 3) ^ (o & 7)) << 3)) + (c & 7);
    g_wf[k * 4096 + idx] = __float2half_rn(v);
}

// ---------------------------------------------------------------------------
// Kernel 3: main deformable conv via mma.sync (HMMA fp16 single-term).
// 512 threads, 2 CTAs/SM. One CTA per (b, h): M=128 px, N=64 o, 9 taps.
// Offsets are computed IN-KERNEL from the (already fp16 NHWC) x row:
//   stage xh[b,h,:,:] (16KB, pad-144B rows) + w_off into dead A0/B0 smem,
//   then fuse the two 64-ch dot products per (tap,pixel) into the geometry
//   table build. No g_off global round-trip.
// Double-buffered A/B -> ONE __syncthreads per tap.
// ---------------------------------------------------------------------------
#define A0_OFF   0          // A tile fp16 buf0: 16KB   (staging: xh row, 18.4KB)
#define A1_OFF   16384      // A tile fp16 buf1: 16KB
#define B0_OFF   32768      // B buf0: 8KB              (staging: w_off, 4.6KB)
#define B1_OFF   40960      // B buf1: 8KB
#define PW_OFF   49152      // tables: weights float4 [9][128] = 18KB
#define PA_OFF   67584      // tables: corner byte-offsets uint4 [9][128] = 18KB
#define SMEM_SZ  86016
#define XROW_STRIDE 144     // padded staging row (128B data + 16B pad): conflict-free

__global__ void __launch_bounds__(512, 2) k_main(float* __restrict__ out,
                                                 const float* __restrict__ w_off,
                                                 const float* __restrict__ b_off) {
    extern __shared__ char smem[];
    uint32_t sb = smem_u32(smem);
    float4* s_pw = (float4*)(smem + PW_OFF);
    uint4*  s_pa = (uint4*)(smem + PA_OFF);

    int t    = threadIdx.x;
    int lane = t & 31;
    int wid  = t >> 5;
    int h    = blockIdx.x & 127;
    int b    = blockIdx.x >> 7;

    const char* xtb = (const char*)(g_xh + (size_t)b * HW_ * C_);

    // ---- Stage xh row (b,h): 16KB contiguous -> padded smem rows; + w_off ----
    {
        const uint4* xrow = (const uint4*)(g_xh + ((size_t)b * HW_ + (size_t)h * W_) * C_);
#pragma unroll
        for (int i = 0; i < 2; i++) {
            int l = t * 2 + i;           // 0..1023 (128 rows x 8 uint4)
            int p = l >> 3, c8 = l & 7;
            uint4 v = __ldg(xrow + l);
            *(uint4*)(smem + A0_OFF + p * XROW_STRIDE + c8 * 16) = v;
        }
        if (t < 288)                     // w_off: 18*64 floats = 288 uint4
            ((uint4*)(smem + B0_OFF))[t] = __ldg((const uint4*)w_off + t);
    }
    __syncthreads();

    // ---- Build tables: offsets (2 dots/item) + bilinear geometry ----
    for (int idx = t; idx < 9 * 128; idx += 512) {
        int k = idx >> 7;                // warp-uniform
        int p = idx & 127;
        float oy = __ldg(b_off + 2 * k);
        float ox = __ldg(b_off + 2 * k + 1);
        const char*   xr = smem + A0_OFF + p * XROW_STRIDE;
        const float4* wy = (const float4*)((const float*)(smem + B0_OFF) + (2 * k) * 64);
        const float4* wx = wy + 16;      // next 64 floats
#pragma unroll
        for (int c8 = 0; c8 < 8; c8++) {
            uint4 u = *(const uint4*)(xr + c8 * 16);
            float2 f0 = h2f2(u.x), f1 = h2f2(u.y), f2 = h2f2(u.z), f3 = h2f2(u.w);
            float4 a0 = wy[c8 * 2], a1 = wy[c8 * 2 + 1];
            float4 b0 = wx[c8 * 2], b1 = wx[c8 * 2 + 1];
            oy = fmaf(f0.x, a0.x, fmaf(f0.y, a0.y, fmaf(f1.x, a0.z, fmaf(f1.y, a0.w, oy))));
            oy = fmaf(f2.x, a1.x, fmaf(f2.y, a1.y, fmaf(f3.x, a1.z, fmaf(f3.y, a1.w, oy))));
            ox = fmaf(f0.x, b0.x, fmaf(f0.y, b0.y, fmaf(f1.x, b0.z, fmaf(f1.y, b0.w, ox))));
            ox = fmaf(f2.x, b1.x, fmaf(f2.y, b1.y, fmaf(f3.x, b1.z, fmaf(f3.y, b1.w, ox))));
        }

        int kh = k / 3;
        int kw = k - kh * 3;
        float py = (float)(h - 1 + kh) + oy;
        float px = (float)(p - 1 + kw) + ox;
        int y0 = __float2int_rd(py);
        int x0 = __float2int_rd(px);
        float wy1 = py - (float)y0, wx1 = px - (float)x0;
        float wy0 = 1.0f - wy1,     wx0 = 1.0f - wx1;
        int y1 = y0 + 1, x1 = x0 + 1;
        bool vy0 = (unsigned)y0 < (unsigned)H_;
        bool vy1 = (unsigned)y1 < (unsigned)H_;
        bool vx0 = (unsigned)x0 < (unsigned)W_;
        bool vx1 = (unsigned)x1 < (unsigned)W_;
        int y0c = min(max(y0, 0), H_ - 1), y1c = min(max(y1, 0), H_ - 1);
        int x0c = min(max(x0, 0), W_ - 1), x1c = min(max(x1, 0), W_ - 1);
        float4 w4;
        w4.x = (vy0 && vx0) ? wy0 * wx0 : 0.0f;
        w4.y = (vy0 && vx1) ? wy0 * wx1 : 0.0f;
        w4.z = (vy1 && vx0) ? wy1 * wx0 : 0.0f;
        w4.w = (vy1 && vx1) ? wy1 * wx1 : 0.0f;
        uint4 a4;
        a4.x = (uint32_t)((y0c * W_ + x0c) << 7);   // *64ch*2B
        a4.y = (uint32_t)((y0c * W_ + x1c) << 7);
        a4.z = (uint32_t)((y1c * W_ + x0c) << 7);
        a4.w = (uint32_t)((y1c * W_ + x1c) << 7);
        s_pw[idx] = w4;
        s_pa[idx] = a4;
    }

    float acc[4][4];
#pragma unroll
    for (int nt = 0; nt < 4; nt++)
#pragma unroll
        for (int j = 0; j < 4; j++) acc[nt][j] = 0.0f;

    // Phase-A mapping: 8-channel granule per thread
    const int pa_cg = t & 7;     // granule 0..7 (16B of fp16 = 8 channels)
    const int pa_p0 = t >> 3;    // pixel within pass (0..63)
    // Warp tile mapping (16 warps)
    const int wm = wid & 7;      // px group: 16*wm .. +15
    const int wn = wid >> 3;     // o  group: 32*wn .. +31
    // ldmatrix lane roles
    const int a_r  = lane & 15;
    const int a_q  = lane >> 4;
    const int b_or = (lane & 7) + ((lane >> 4) << 3);
    const int b_qb = (lane >> 3) & 1;

    __syncthreads();   // tables ready; staging areas now reusable as A0/B0

    for (int k = 0; k < 9; k++) {
        const int buf = k & 1;
        char* a_buf = smem + (buf ? A1_OFF : A0_OFF);
        char* b_buf = smem + (buf ? B1_OFF : B0_OFF);

        // prefetch B_k into registers (hidden behind sampling)
        uint4 wb;
        {
            const uint4* sh = (const uint4*)g_wf + (size_t)k * 512;
            wb = __ldg(sh + t);
        }

        // ---- Phase A: fp16 gather + fp32 bilinear -> fp16 A tile (buf) ----
        const float4* pwk = s_pw + k * 128;
        const uint4*  pak = s_pa + k * 128;
#pragma unroll
        for (int pass = 0; pass < 2; pass++) {
            int p = pass * 64 + pa_p0;
            float4 w4 = pwk[p];
            uint4  a4 = pak[p];
            int cb = pa_cg * 16;   // granule byte offset (8 fp16 channels)

            uint4 u0 = __ldg((const uint4*)(xtb + a4.x + cb));
            uint4 u1 = __ldg((const uint4*)(xtb + a4.y + cb));
            uint4 u2 = __ldg((const uint4*)(xtb + a4.z + cb));
            uint4 u3 = __ldg((const uint4*)(xtb + a4.w + cb));

            uint32_t c0a[4] = {u0.x, u0.y, u0.z, u0.w};
            uint32_t c1a[4] = {u1.x, u1.y, u1.z, u1.w};
            uint32_t c2a[4] = {u2.x, u2.y, u2.z, u2.w};
            uint32_t c3a[4] = {u3.x, u3.y, u3.z, u3.w};

            float2 s[4];
#pragma unroll
            for (int j = 0; j < 4; j++) {
                float2 f = h2f2(c0a[j]);
                s[j].x = w4.x * f.x;
                s[j].y = w4.x * f.y;
            }
#pragma unroll
            for (int j = 0; j < 4; j++) {
                float2 f = h2f2(c1a[j]);
                s[j].x = fmaf(w4.y, f.x, s[j].x);
                s[j].y = fmaf(w4.y, f.y, s[j].y);
            }
#pragma unroll
            for (int j = 0; j < 4; j++) {
                float2 f = h2f2(c2a[j]);
                s[j].x = fmaf(w4.z, f.x, s[j].x);
                s[j].y = fmaf(w4.z, f.y, s[j].y);
            }
#pragma unroll
            for (int j = 0; j < 4; j++) {
                float2 f = h2f2(c3a[j]);
                s[j].x = fmaf(w4.w, f.x, s[j].x);
                s[j].y = fmaf(w4.w, f.y, s[j].y);
            }

            uint4 o;
            o.x = cvt2h(s[0].y, s[0].x);   // low half = lower channel
            o.y = cvt2h(s[1].y, s[1].x);
            o.z = cvt2h(s[2].y, s[2].x);
            o.w = cvt2h(s[3].y, s[3].x);

            int chunk = pa_cg ^ (p & 7);
            *(uint4*)(a_buf + p * 128 + chunk * 16) = o;
        }

        // store prefetched B (pre-swizzled layout): 512 threads x 16B = 8KB
        ((uint4*)b_buf)[t] = wb;

        __syncthreads();   // A(k), B(k) ready; also releases buf for k+2's writes

        // ---- Phase B: HMMA over 4 k-tiles, single fp16 term ----
        uint32_t a_base = sb + (buf ? A1_OFF : A0_OFF);
        uint32_t b_base = sb + (buf ? B1_OFF : B0_OFF);
#pragma unroll
        for (int kt = 0; kt < 4; kt++) {
            uint32_t af[4];
            {
                int row = wm * 16 + a_r;
                uint32_t ad = a_base + row * 128 +
                              (((2 * kt + a_q) ^ (a_r & 7)) * 16);
                LDMX4(af, ad);
            }
            uint32_t bf[2][4];
#pragma unroll
            for (int j = 0; j < 2; j++) {
                int o = wn * 32 + j * 16 + b_or;
                uint32_t bd = b_base + o * 128 +
                              (((2 * kt + b_qb) ^ (o & 7)) * 16);
                LDMX4(bf[j], bd);
            }
#pragma unroll
            for (int nt = 0; nt < 4; nt++) {
                const uint32_t* bp = &bf[nt >> 1][(nt & 1) * 2];
                MMA16816H(acc[nt], af, bp[0], bp[1]);
            }
        }
    }

    // ---- Epilogue: direct STG ----
    {
        int px = wm * 16 + (lane >> 2);
#pragma unroll
        for (int nt = 0; nt < 4; nt++) {
            int o0 = wn * 32 + nt * 8 + 2 * (lane & 3);
            float* ob = out + ((size_t)(b * 64 + o0)) * HW_ + (size_t)h * W_;
            ob[px]           = acc[nt][0];
            ob[HW_ + px]     = acc[nt][1];
            ob[px + 8]       = acc[nt][2];
            ob[HW_ + px + 8] = acc[nt][3];
        }
    }
}

// ---------------------------------------------------------------------------
extern "C" void kernel_launch(void* const* d_in, const int* in_sizes, int n_in,
                              void* d_out, int out_size) {
    const float* x     = (const float*)d_in[0];   // (8,64,128,128)
    const float* wght  = (const float*)d_in[1];   // (64,64,3,3)
    const float* w_off = (const float*)d_in[2];   // (18,64)
    const float* b_off = (const float*)d_in[3];   // (18,)
    float* out = (float*)d_out;                   // (8,64,128,128)

    k_transpose<<<dim3(HW_ / 32, C_ / 32, B_), dim3(32, 8)>>>(x);
    k_reorder_w<<<(K2_ * O_ * C_ + 255) / 256, 256>>>(wght);

    cudaFuncSetAttribute(k_main, cudaFuncAttributeMaxDynamicSharedMemorySize,
                         SMEM_SZ);
    k_main<<<B_ * H_, 512, SMEM_SZ>>>(out, w_off, b_off);
}